// round 1
// baseline (speedup 1.0000x reference)
#include <cuda_runtime.h>
#include <math.h>

// Problem constants
#define BB   2
#define SS   2048
#define DM   1024
#define NH   16
#define DH   64
#define MM   (BB*SS)        // 4096 rows for projections

// -------- scratch (device globals; allocation-free) --------
__device__ float g_q[BB*NH*SS*DH];    // [b][h][s][d]
__device__ float g_k[BB*NH*SS*DH];
__device__ float g_v[BB*NH*SS*DH];
__device__ float g_ctx[MM*DM];        // [b*S+s][h*64+d]

// ============================================================
// GEMM: out = X @ W^T + bias     (X: MMxDM, W: DMxDM both row-major, K contiguous)
// 128x128 block, BK=8, 256 threads, 8x8 microtile.
// ============================================================

__global__ __launch_bounds__(256) void qkv_gemm(
    const float* __restrict__ X,
    const float* __restrict__ Wq, const float* __restrict__ bq,
    const float* __restrict__ Wk, const float* __restrict__ bk,
    const float* __restrict__ Wv, const float* __restrict__ bv)
{
    const float* W; const float* bias; float* out;
    if (blockIdx.z == 0)      { W = Wq; bias = bq; out = g_q; }
    else if (blockIdx.z == 1) { W = Wk; bias = bk; out = g_k; }
    else                      { W = Wv; bias = bv; out = g_v; }

    __shared__ float As[8][128];
    __shared__ float Bs[8][128];

    const int tid = threadIdx.x;
    const int bm = blockIdx.y * 128;
    const int bn = blockIdx.x * 128;
    const int lr = tid >> 1;            // 0..127
    const int lk = (tid & 1) * 4;       // 0 or 4
    const int ty = tid >> 4;            // 0..15
    const int tx = tid & 15;            // 0..15

    float acc[8][8];
    #pragma unroll
    for (int i = 0; i < 8; i++)
        #pragma unroll
        for (int j = 0; j < 8; j++) acc[i][j] = 0.f;

    for (int k0 = 0; k0 < DM; k0 += 8) {
        float4 a = *(const float4*)(X + (size_t)(bm + lr) * DM + k0 + lk);
        float4 w = *(const float4*)(W + (size_t)(bn + lr) * DM + k0 + lk);
        As[lk + 0][lr] = a.x; As[lk + 1][lr] = a.y; As[lk + 2][lr] = a.z; As[lk + 3][lr] = a.w;
        Bs[lk + 0][lr] = w.x; Bs[lk + 1][lr] = w.y; Bs[lk + 2][lr] = w.z; Bs[lk + 3][lr] = w.w;
        __syncthreads();
        #pragma unroll
        for (int k = 0; k < 8; k++) {
            float ra[8], rb[8];
            #pragma unroll
            for (int i = 0; i < 8; i++) { ra[i] = As[k][ty * 8 + i]; rb[i] = Bs[k][tx * 8 + i]; }
            #pragma unroll
            for (int i = 0; i < 8; i++)
                #pragma unroll
                for (int j = 0; j < 8; j++) acc[i][j] += ra[i] * rb[j];
        }
        __syncthreads();
    }

    // epilogue: add bias, write to [b][h][s][d]
    const int n0 = bn + tx * 8;
    const int h  = n0 >> 6;          // 8 | 64 -> whole microtile row is in one head
    const int d0 = n0 & 63;
    #pragma unroll
    for (int i = 0; i < 8; i++) {
        const int m = bm + ty * 8 + i;
        const int b = m >> 11;       // /2048
        const int s = m & 2047;
        float* dst = out + ((((size_t)b * NH + h) * SS + s) * DH + d0);
        float4 v0, v1;
        v0.x = acc[i][0] + bias[n0 + 0]; v0.y = acc[i][1] + bias[n0 + 1];
        v0.z = acc[i][2] + bias[n0 + 2]; v0.w = acc[i][3] + bias[n0 + 3];
        v1.x = acc[i][4] + bias[n0 + 4]; v1.y = acc[i][5] + bias[n0 + 5];
        v1.z = acc[i][6] + bias[n0 + 6]; v1.w = acc[i][7] + bias[n0 + 7];
        *(float4*)(dst + 0) = v0;
        *(float4*)(dst + 4) = v1;
    }
}

__global__ __launch_bounds__(256) void out_gemm(
    const float* __restrict__ Wo, const float* __restrict__ bo,
    float* __restrict__ out)
{
    __shared__ float As[8][128];
    __shared__ float Bs[8][128];

    const int tid = threadIdx.x;
    const int bm = blockIdx.y * 128;
    const int bn = blockIdx.x * 128;
    const int lr = tid >> 1;
    const int lk = (tid & 1) * 4;
    const int ty = tid >> 4;
    const int tx = tid & 15;

    float acc[8][8];
    #pragma unroll
    for (int i = 0; i < 8; i++)
        #pragma unroll
        for (int j = 0; j < 8; j++) acc[i][j] = 0.f;

    for (int k0 = 0; k0 < DM; k0 += 8) {
        float4 a = *(const float4*)(g_ctx + (size_t)(bm + lr) * DM + k0 + lk);
        float4 w = *(const float4*)(Wo + (size_t)(bn + lr) * DM + k0 + lk);
        As[lk + 0][lr] = a.x; As[lk + 1][lr] = a.y; As[lk + 2][lr] = a.z; As[lk + 3][lr] = a.w;
        Bs[lk + 0][lr] = w.x; Bs[lk + 1][lr] = w.y; Bs[lk + 2][lr] = w.z; Bs[lk + 3][lr] = w.w;
        __syncthreads();
        #pragma unroll
        for (int k = 0; k < 8; k++) {
            float ra[8], rb[8];
            #pragma unroll
            for (int i = 0; i < 8; i++) { ra[i] = As[k][ty * 8 + i]; rb[i] = Bs[k][tx * 8 + i]; }
            #pragma unroll
            for (int i = 0; i < 8; i++)
                #pragma unroll
                for (int j = 0; j < 8; j++) acc[i][j] += ra[i] * rb[j];
        }
        __syncthreads();
    }

    const int n0 = bn + tx * 8;
    #pragma unroll
    for (int i = 0; i < 8; i++) {
        const int m = bm + ty * 8 + i;
        float* dst = out + (size_t)m * DM + n0;
        float4 v0, v1;
        v0.x = acc[i][0] + bo[n0 + 0]; v0.y = acc[i][1] + bo[n0 + 1];
        v0.z = acc[i][2] + bo[n0 + 2]; v0.w = acc[i][3] + bo[n0 + 3];
        v1.x = acc[i][4] + bo[n0 + 4]; v1.y = acc[i][5] + bo[n0 + 5];
        v1.z = acc[i][6] + bo[n0 + 6]; v1.w = acc[i][7] + bo[n0 + 7];
        *(float4*)(dst + 0) = v0;
        *(float4*)(dst + 4) = v1;
    }
}

// ============================================================
// Flash attention, fp32, causal. 64x64 tiles, online softmax.
// Grid: (S/64 query tiles, B*H). 256 threads, 4x4 microtiles.
// Dynamic smem layout (floats):
//   QsT[64][64]  (QsT[d][r])            @ 0
//   KVs[64][64]  (KsT[d][c] / Vs[t][d]) @ 4096
//   SsT[64][68]  (SsT[t][r], padded)    @ 8192
//   mrow[64], lrow[64], crow[64]        @ 12544
// ============================================================
#define SST_STRIDE 68
#define ATTN_SMEM_FLOATS (4096 + 4096 + 64*SST_STRIDE + 3*64)
#define ATTN_SMEM_BYTES  (ATTN_SMEM_FLOATS * 4)

__global__ __launch_bounds__(256) void attn_kernel()
{
    extern __shared__ float sm[];
    float* QsT  = sm;
    float* KVs  = sm + 4096;
    float* SsT  = sm + 8192;
    float* mrow = sm + 8192 + 64 * SST_STRIDE;
    float* lrow = mrow + 64;
    float* crow = lrow + 64;

    const int tid = threadIdx.x;
    const int it  = blockIdx.x;           // query tile
    const int bh  = blockIdx.y;           // b*NH + h
    const float* Qb = g_q + (size_t)bh * SS * DH + (size_t)it * 64 * DH;
    const float* Kb = g_k + (size_t)bh * SS * DH;
    const float* Vb = g_v + (size_t)bh * SS * DH;

    // load Q tile transposed: QsT[d][r]
    {
        const int r  = tid >> 2;
        const int c0 = (tid & 3) * 4;
        #pragma unroll
        for (int rep = 0; rep < 4; rep++) {
            const int c = c0 + rep * 16;
            float4 q = *(const float4*)(Qb + r * DH + c);
            QsT[(c + 0) * 64 + r] = q.x;
            QsT[(c + 1) * 64 + r] = q.y;
            QsT[(c + 2) * 64 + r] = q.z;
            QsT[(c + 3) * 64 + r] = q.w;
        }
    }
    if (tid < 64) { mrow[tid] = -1e30f; lrow[tid] = 0.f; }

    const int ty = tid >> 4, tx = tid & 15;
    const int r0 = ty * 4, c0 = tx * 4;

    float acc[4][4];
    #pragma unroll
    for (int i = 0; i < 4; i++)
        #pragma unroll
        for (int j = 0; j < 4; j++) acc[i][j] = 0.f;

    for (int jt = 0; jt <= it; jt++) {
        // ---- load K tile transposed into KVs: KsT[d][c] ----
        {
            const int r  = tid >> 2;
            const int cc = (tid & 3) * 4;
            #pragma unroll
            for (int rep = 0; rep < 4; rep++) {
                const int c = cc + rep * 16;
                float4 k4 = *(const float4*)(Kb + (size_t)(jt * 64 + r) * DH + c);
                KVs[(c + 0) * 64 + r] = k4.x;
                KVs[(c + 1) * 64 + r] = k4.y;
                KVs[(c + 2) * 64 + r] = k4.z;
                KVs[(c + 3) * 64 + r] = k4.w;
            }
        }
        __syncthreads();

        // ---- scores: s[i][j] = sum_d Q[r0+i][d]*K[c0+j][d] ----
        float s[4][4];
        #pragma unroll
        for (int i = 0; i < 4; i++)
            #pragma unroll
            for (int j = 0; j < 4; j++) s[i][j] = 0.f;

        #pragma unroll 8
        for (int d = 0; d < 64; d++) {
            float ra[4], rb[4];
            *(float4*)ra = *(const float4*)&QsT[d * 64 + r0];
            *(float4*)rb = *(const float4*)&KVs[d * 64 + c0];
            #pragma unroll
            for (int i = 0; i < 4; i++)
                #pragma unroll
                for (int j = 0; j < 4; j++) s[i][j] += ra[i] * rb[j];
        }

        // ---- scale, mask (diag tile only), store SsT[c][r] ----
        const bool diag = (jt == it);
        #pragma unroll
        for (int i = 0; i < 4; i++) {
            #pragma unroll
            for (int j = 0; j < 4; j++) {
                float v = s[i][j] * 0.125f;
                if (diag && (c0 + j) > (r0 + i)) v = -1e30f;
                SsT[(c0 + j) * SST_STRIDE + (r0 + i)] = v;
            }
        }
        __syncthreads();

        // ---- online softmax per query row (threads 0..63) ----
        if (tid < 64) {
            const int r = tid;
            float mold = mrow[r];
            float tm = -1e30f;
            #pragma unroll 8
            for (int t = 0; t < 64; t++) tm = fmaxf(tm, SsT[t * SST_STRIDE + r]);
            float mnew = fmaxf(mold, tm);
            float corr = __expf(mold - mnew);
            float sum = 0.f;
            #pragma unroll 8
            for (int t = 0; t < 64; t++) {
                float p = __expf(SsT[t * SST_STRIDE + r] - mnew);
                SsT[t * SST_STRIDE + r] = p;
                sum += p;
            }
            mrow[r] = mnew;
            lrow[r] = lrow[r] * corr + sum;
            crow[r] = corr;
        }
        __syncthreads();

        // ---- rescale accumulator, load V tile (natural [t][d]) ----
        #pragma unroll
        for (int i = 0; i < 4; i++) {
            const float cr = crow[r0 + i];
            #pragma unroll
            for (int j = 0; j < 4; j++) acc[i][j] *= cr;
        }
        {
            const float4* src = (const float4*)(Vb + (size_t)jt * 64 * DH);
            float4* dst = (float4*)KVs;
            #pragma unroll
            for (int rep = 0; rep < 4; rep++) dst[tid + rep * 256] = src[tid + rep * 256];
        }
        __syncthreads();

        // ---- O += P @ V ----
        #pragma unroll 8
        for (int t = 0; t < 64; t++) {
            float ra[4], rb[4];
            *(float4*)ra = *(const float4*)&SsT[t * SST_STRIDE + r0];
            *(float4*)rb = *(const float4*)&KVs[t * 64 + c0];
            #pragma unroll
            for (int i = 0; i < 4; i++)
                #pragma unroll
                for (int j = 0; j < 4; j++) acc[i][j] += ra[i] * rb[j];
        }
        __syncthreads();
    }

    // ---- epilogue: normalize, write ctx[b*S+s][h*64+d] ----
    const int b = bh >> 4;
    const int h = bh & 15;
    #pragma unroll
    for (int i = 0; i < 4; i++) {
        const int r = r0 + i;
        const float inv = 1.f / lrow[r];
        const int s = it * 64 + r;
        float* dst = g_ctx + ((size_t)b * SS + s) * DM + h * 64 + c0;
        float4 v;
        v.x = acc[i][0] * inv; v.y = acc[i][1] * inv;
        v.z = acc[i][2] * inv; v.w = acc[i][3] * inv;
        *(float4*)dst = v;
    }
}

// ============================================================
extern "C" void kernel_launch(void* const* d_in, const int* in_sizes, int n_in,
                              void* d_out, int out_size)
{
    const float* x  = (const float*)d_in[0];
    const float* Wq = (const float*)d_in[1];
    const float* bq = (const float*)d_in[2];
    const float* Wk = (const float*)d_in[3];
    const float* bk = (const float*)d_in[4];
    const float* Wv = (const float*)d_in[5];
    const float* bv = (const float*)d_in[6];
    const float* Wo = (const float*)d_in[7];
    const float* bo = (const float*)d_in[8];
    float* out = (float*)d_out;

    cudaFuncSetAttribute(attn_kernel, cudaFuncAttributeMaxDynamicSharedMemorySize,
                         ATTN_SMEM_BYTES);

    qkv_gemm<<<dim3(DM / 128, MM / 128, 3), 256>>>(x, Wq, bq, Wk, bk, Wv, bv);
    attn_kernel<<<dim3(SS / 64, BB * NH), 256, ATTN_SMEM_BYTES>>>();
    out_gemm<<<dim3(DM / 128, MM / 128), 256>>>(Wo, bo, out);
}

// round 5
// speedup vs baseline: 1.3675x; 1.3675x over previous
#include <cuda_runtime.h>
#include <cuda_bf16.h>
#include <cstdint>
#include <math.h>

// Problem constants
#define BB   2
#define SS   2048
#define DM   1024
#define NH   16
#define DH   64
#define MM   (BB*SS)

// -------- scratch (device globals; allocation-free) --------
__device__ float g_q[BB*NH*SS*DH];    // [b][h][s][d]
__device__ float g_k[BB*NH*SS*DH];
__device__ float g_v[BB*NH*SS*DH];
__device__ float g_ctx[MM*DM];        // [b*S+s][h*64+d]

// ============================================================
// helpers
// ============================================================
__device__ __forceinline__ uint32_t smem_u32(const void* p) {
    uint32_t a;
    asm("{ .reg .u64 t; cvta.to.shared.u64 t, %1; cvt.u32.u64 %0, t; }" : "=r"(a) : "l"(p));
    return a;
}

#define LDSM4(d0, d1, d2, d3, addr)                                            \
    asm volatile("ldmatrix.sync.aligned.m8n8.x4.shared.b16 {%0,%1,%2,%3}, [%4];" \
                 : "=r"(d0), "=r"(d1), "=r"(d2), "=r"(d3) : "r"(addr))

#define MMA16816(c, a0, a1, a2, a3, b0, b1)                                    \
    asm volatile("mma.sync.aligned.m16n8k16.row.col.f32.bf16.bf16.f32 "        \
                 "{%0,%1,%2,%3}, {%4,%5,%6,%7}, {%8,%9}, {%0,%1,%2,%3};"       \
                 : "+f"((c)[0]), "+f"((c)[1]), "+f"((c)[2]), "+f"((c)[3])      \
                 : "r"(a0), "r"(a1), "r"(a2), "r"(a3), "r"(b0), "r"(b1))

// ============================================================
// bf16-split tensor-core GEMM:  out = A @ W^T + bias
// A: [Mrows,1024] fp32 rm, W: [1024,1024] fp32 rm (k contiguous both).
// CTA 128x128, BK=64, 256 threads = 8 warps in 2x4 grid (warp tile 64x32).
// SMEM per stage: Ahi/Alo/Bhi/Blo 128x64 bf16, swizzled 128B rows.
// MODE 0: QKV (blockIdx.z selects), epilogue scatters to [b][h][s][d]
// MODE 1: output projection, epilogue row-major to d_out
// ============================================================
#define TILE_B   16384                // bytes per 128x64 bf16 tile
#define STAGE_B  (4*TILE_B)           // Ahi Alo Bhi Blo
#define GEMM_SMEM_BYTES (1024 + 2*STAGE_B)

// convert 8 fp32 (2 float4) -> 8 bf16 hi + 8 bf16 lo, store 16B each, swizzled
__device__ __forceinline__ void conv_sts(const float4& u, const float4& v,
                                         char* hi_tile, char* lo_tile,
                                         int r, int chunk_logical)
{
    const int chunk = chunk_logical ^ (r & 7);
    const int off = r * 128 + chunk * 16;
    __nv_bfloat162 h01 = __floats2bfloat162_rn(u.x, u.y);
    __nv_bfloat162 h23 = __floats2bfloat162_rn(u.z, u.w);
    __nv_bfloat162 h45 = __floats2bfloat162_rn(v.x, v.y);
    __nv_bfloat162 h67 = __floats2bfloat162_rn(v.z, v.w);
    uint4 hv = make_uint4(*(uint32_t*)&h01, *(uint32_t*)&h23,
                          *(uint32_t*)&h45, *(uint32_t*)&h67);
    float4 lu, lv;
    lu.x = u.x - __bfloat162float(h01.x); lu.y = u.y - __bfloat162float(h01.y);
    lu.z = u.z - __bfloat162float(h23.x); lu.w = u.w - __bfloat162float(h23.y);
    lv.x = v.x - __bfloat162float(h45.x); lv.y = v.y - __bfloat162float(h45.y);
    lv.z = v.z - __bfloat162float(h67.x); lv.w = v.w - __bfloat162float(h67.y);
    __nv_bfloat162 l01 = __floats2bfloat162_rn(lu.x, lu.y);
    __nv_bfloat162 l23 = __floats2bfloat162_rn(lu.z, lu.w);
    __nv_bfloat162 l45 = __floats2bfloat162_rn(lv.x, lv.y);
    __nv_bfloat162 l67 = __floats2bfloat162_rn(lv.z, lv.w);
    uint4 lw = make_uint4(*(uint32_t*)&l01, *(uint32_t*)&l23,
                          *(uint32_t*)&l45, *(uint32_t*)&l67);
    *(uint4*)(hi_tile + off) = hv;
    *(uint4*)(lo_tile + off) = lw;
}

template<int MODE>
__global__ __launch_bounds__(256, 1) void gemm_tc(
    const float* __restrict__ X,
    const float* __restrict__ W1, const float* __restrict__ b1,
    const float* __restrict__ W2, const float* __restrict__ b2,
    const float* __restrict__ W3, const float* __restrict__ b3,
    float* __restrict__ outp)
{
    extern __shared__ char smraw[];
    char* tiles = (char*)(((uintptr_t)smraw + 1023) & ~(uintptr_t)1023);
    const uint32_t tiles32 = smem_u32(tiles);

    const int tid  = threadIdx.x;
    const int wid  = tid >> 5;
    const int lane = tid & 31;
    const int bm = blockIdx.y * 128;
    const int bn = blockIdx.x * 128;

    const float* A;
    const float* W;
    const float* bias;
    if (MODE == 0) {
        A = X;
        const int z = blockIdx.z;
        W    = (z == 0) ? W1 : (z == 1) ? W2 : W3;
        bias = (z == 0) ? b1 : (z == 1) ? b2 : b3;
    } else {
        A = g_ctx; W = W1; bias = b1;
    }

    // fill indexing: 2 threads per row, 32 floats each
    const int r    = tid >> 1;
    const int half = tid & 1;
    const float* arow = A + (size_t)(bm + r) * DM + half * 32;
    const float* wrow = W + (size_t)(bn + r) * DM + half * 32;

    // ldmatrix lane addressing
    const int lrow = (lane & 7) | (((lane >> 3) & 1) << 3);  // 0..15
    const int lkh  = lane >> 4;                              // k half 0/1
    const int r7   = lane & 7;
    const int wm   = (wid >> 2) * 64;    // warp m offset (0/64)
    const int wn   = (wid & 3) * 32;     // warp n offset

    float acc[4][4][4];
    #pragma unroll
    for (int i = 0; i < 4; i++)
        #pragma unroll
        for (int j = 0; j < 4; j++)
            #pragma unroll
            for (int c = 0; c < 4; c++) acc[i][j][c] = 0.f;

    float4 pf[8];

    // ---- prologue: fill stage 0 (kb = 0) ----
    {
        char* st = tiles;
        #pragma unroll
        for (int v = 0; v < 8; v++) pf[v] = ((const float4*)arow)[v];
        #pragma unroll
        for (int g = 0; g < 4; g++)
            conv_sts(pf[2*g], pf[2*g+1], st, st + TILE_B, r, half*4 + g);
        #pragma unroll
        for (int v = 0; v < 8; v++) pf[v] = ((const float4*)wrow)[v];
        #pragma unroll
        for (int g = 0; g < 4; g++)
            conv_sts(pf[2*g], pf[2*g+1], st + 2*TILE_B, st + 3*TILE_B, r, half*4 + g);
    }
    __syncthreads();

    for (int kb = 0; kb < 16; kb++) {
        const int j = kb & 1;
        const uint32_t Ahi = tiles32 + j * STAGE_B;
        const uint32_t Alo = Ahi + TILE_B;
        const uint32_t Bhi = Ahi + 2*TILE_B;
        const uint32_t Blo = Ahi + 3*TILE_B;
        char* nst = tiles + (j ^ 1) * STAGE_B;
        const bool more = (kb < 15);

        // prefetch next A
        if (more) {
            const float* src = arow + (kb + 1) * 64;
            #pragma unroll
            for (int v = 0; v < 8; v++) pf[v] = ((const float4*)src)[v];
        }

        // compute k16 = 0,1
        #pragma unroll
        for (int k16 = 0; k16 < 2; k16++) {
            uint32_t ahi[4][4], alo[4][4], bhi[2][4], blo[2][4];
            const int ck = ((2*k16 + lkh) ^ r7) * 16;
            #pragma unroll
            for (int i = 0; i < 4; i++) {
                const uint32_t ro = (uint32_t)(wm + i*16 + lrow) * 128 + ck;
                LDSM4(ahi[i][0], ahi[i][1], ahi[i][2], ahi[i][3], Ahi + ro);
                LDSM4(alo[i][0], alo[i][1], alo[i][2], alo[i][3], Alo + ro);
            }
            #pragma unroll
            for (int p = 0; p < 2; p++) {
                const uint32_t ro = (uint32_t)(wn + p*16 + lrow) * 128 + ck;
                LDSM4(bhi[p][0], bhi[p][1], bhi[p][2], bhi[p][3], Bhi + ro);
                LDSM4(blo[p][0], blo[p][1], blo[p][2], blo[p][3], Blo + ro);
            }
            // B fragment pairing: ldmatrix gives d0=(n0-7,klo) d1=(n8-15,klo)
            // d2=(n0-7,khi) d3=(n8-15,khi); mma needs (klo,khi) of SAME n-group.
            #pragma unroll
            for (int i = 0; i < 4; i++)
                #pragma unroll
                for (int jn = 0; jn < 4; jn++) {
                    const int p = jn >> 1, q = jn & 1;
                    MMA16816(acc[i][jn], ahi[i][0], ahi[i][1], ahi[i][2], ahi[i][3],
                             bhi[p][q], bhi[p][q+2]);
                    MMA16816(acc[i][jn], ahi[i][0], ahi[i][1], ahi[i][2], ahi[i][3],
                             blo[p][q], blo[p][q+2]);
                    MMA16816(acc[i][jn], alo[i][0], alo[i][1], alo[i][2], alo[i][3],
                             bhi[p][q], bhi[p][q+2]);
                }
        }

        // store next A, prefetch next B
        if (more) {
            #pragma unroll
            for (int g = 0; g < 4; g++)
                conv_sts(pf[2*g], pf[2*g+1], nst, nst + TILE_B, r, half*4 + g);
            const float* src = wrow + (kb + 1) * 64;
            #pragma unroll
            for (int v = 0; v < 8; v++) pf[v] = ((const float4*)src)[v];
        }

        // compute k16 = 2,3
        #pragma unroll
        for (int k16 = 2; k16 < 4; k16++) {
            uint32_t ahi[4][4], alo[4][4], bhi[2][4], blo[2][4];
            const int ck = ((2*k16 + lkh) ^ r7) * 16;
            #pragma unroll
            for (int i = 0; i < 4; i++) {
                const uint32_t ro = (uint32_t)(wm + i*16 + lrow) * 128 + ck;
                LDSM4(ahi[i][0], ahi[i][1], ahi[i][2], ahi[i][3], Ahi + ro);
                LDSM4(alo[i][0], alo[i][1], alo[i][2], alo[i][3], Alo + ro);
            }
            #pragma unroll
            for (int p = 0; p < 2; p++) {
                const uint32_t ro = (uint32_t)(wn + p*16 + lrow) * 128 + ck;
                LDSM4(bhi[p][0], bhi[p][1], bhi[p][2], bhi[p][3], Bhi + ro);
                LDSM4(blo[p][0], blo[p][1], blo[p][2], blo[p][3], Blo + ro);
            }
            #pragma unroll
            for (int i = 0; i < 4; i++)
                #pragma unroll
                for (int jn = 0; jn < 4; jn++) {
                    const int p = jn >> 1, q = jn & 1;
                    MMA16816(acc[i][jn], ahi[i][0], ahi[i][1], ahi[i][2], ahi[i][3],
                             bhi[p][q], bhi[p][q+2]);
                    MMA16816(acc[i][jn], ahi[i][0], ahi[i][1], ahi[i][2], ahi[i][3],
                             blo[p][q], blo[p][q+2]);
                    MMA16816(acc[i][jn], alo[i][0], alo[i][1], alo[i][2], alo[i][3],
                             bhi[p][q], bhi[p][q+2]);
                }
        }

        // store next B
        if (more) {
            #pragma unroll
            for (int g = 0; g < 4; g++)
                conv_sts(pf[2*g], pf[2*g+1], nst + 2*TILE_B, nst + 3*TILE_B, r, half*4 + g);
        }
        __syncthreads();
    }

    // ---- epilogue: D-fragment scatter + bias ----
    const int qrow = lane >> 2;          // 0..7
    const int qcol = (lane & 3) * 2;     // 0,2,4,6
    #pragma unroll
    for (int jn = 0; jn < 4; jn++) {
        const int col = bn + wn + jn*8 + qcol;
        const float bx = bias[col], by = bias[col + 1];
        #pragma unroll
        for (int i = 0; i < 4; i++) {
            const int row0 = bm + wm + i*16 + qrow;
            #pragma unroll
            for (int hh = 0; hh < 2; hh++) {
                const int row = row0 + hh*8;
                float2 o;
                o.x = acc[i][jn][2*hh+0] + bx;
                o.y = acc[i][jn][2*hh+1] + by;
                float* dst;
                if (MODE == 0) {
                    const int z = blockIdx.z;
                    float* out = (z == 0) ? g_q : (z == 1) ? g_k : g_v;
                    const int b = row >> 11;
                    const int s = row & 2047;
                    const int h = col >> 6;
                    const int d = col & 63;
                    dst = out + ((((size_t)b * NH + h) * SS + s) * DH + d);
                } else {
                    dst = outp + (size_t)row * DM + col;
                }
                *(float2*)dst = o;
            }
        }
    }
}

// ============================================================
// Flash attention, fp32, causal. 64x64 tiles, online softmax.
// (unchanged — verified in round 1)
// ============================================================
#define SST_STRIDE 68
#define ATTN_SMEM_FLOATS (4096 + 4096 + 64*SST_STRIDE + 3*64)
#define ATTN_SMEM_BYTES  (ATTN_SMEM_FLOATS * 4)

__global__ __launch_bounds__(256) void attn_kernel()
{
    extern __shared__ float smf[];
    float* QsT  = smf;
    float* KVs  = smf + 4096;
    float* SsT  = smf + 8192;
    float* mrow = smf + 8192 + 64 * SST_STRIDE;
    float* lrow = mrow + 64;
    float* crow = lrow + 64;

    const int tid = threadIdx.x;
    const int it  = blockIdx.x;
    const int bh  = blockIdx.y;
    const float* Qb = g_q + (size_t)bh * SS * DH + (size_t)it * 64 * DH;
    const float* Kb = g_k + (size_t)bh * SS * DH;
    const float* Vb = g_v + (size_t)bh * SS * DH;

    {
        const int r  = tid >> 2;
        const int c0 = (tid & 3) * 4;
        #pragma unroll
        for (int rep = 0; rep < 4; rep++) {
            const int c = c0 + rep * 16;
            float4 q = *(const float4*)(Qb + r * DH + c);
            QsT[(c + 0) * 64 + r] = q.x;
            QsT[(c + 1) * 64 + r] = q.y;
            QsT[(c + 2) * 64 + r] = q.z;
            QsT[(c + 3) * 64 + r] = q.w;
        }
    }
    if (tid < 64) { mrow[tid] = -1e30f; lrow[tid] = 0.f; }

    const int ty = tid >> 4, tx = tid & 15;
    const int r0 = ty * 4, c0 = tx * 4;

    float acc[4][4];
    #pragma unroll
    for (int i = 0; i < 4; i++)
        #pragma unroll
        for (int j = 0; j < 4; j++) acc[i][j] = 0.f;

    for (int jt = 0; jt <= it; jt++) {
        {
            const int r  = tid >> 2;
            const int cc = (tid & 3) * 4;
            #pragma unroll
            for (int rep = 0; rep < 4; rep++) {
                const int c = cc + rep * 16;
                float4 k4 = *(const float4*)(Kb + (size_t)(jt * 64 + r) * DH + c);
                KVs[(c + 0) * 64 + r] = k4.x;
                KVs[(c + 1) * 64 + r] = k4.y;
                KVs[(c + 2) * 64 + r] = k4.z;
                KVs[(c + 3) * 64 + r] = k4.w;
            }
        }
        __syncthreads();

        float s[4][4];
        #pragma unroll
        for (int i = 0; i < 4; i++)
            #pragma unroll
            for (int j = 0; j < 4; j++) s[i][j] = 0.f;

        #pragma unroll 8
        for (int d = 0; d < 64; d++) {
            float ra[4], rb[4];
            *(float4*)ra = *(const float4*)&QsT[d * 64 + r0];
            *(float4*)rb = *(const float4*)&KVs[d * 64 + c0];
            #pragma unroll
            for (int i = 0; i < 4; i++)
                #pragma unroll
                for (int j = 0; j < 4; j++) s[i][j] += ra[i] * rb[j];
        }

        const bool diag = (jt == it);
        #pragma unroll
        for (int i = 0; i < 4; i++) {
            #pragma unroll
            for (int j = 0; j < 4; j++) {
                float v = s[i][j] * 0.125f;
                if (diag && (c0 + j) > (r0 + i)) v = -1e30f;
                SsT[(c0 + j) * SST_STRIDE + (r0 + i)] = v;
            }
        }
        __syncthreads();

        if (tid < 64) {
            const int rr = tid;
            float mold = mrow[rr];
            float tm = -1e30f;
            #pragma unroll 8
            for (int t = 0; t < 64; t++) tm = fmaxf(tm, SsT[t * SST_STRIDE + rr]);
            float mnew = fmaxf(mold, tm);
            float corr = __expf(mold - mnew);
            float sum = 0.f;
            #pragma unroll 8
            for (int t = 0; t < 64; t++) {
                float p = __expf(SsT[t * SST_STRIDE + rr] - mnew);
                SsT[t * SST_STRIDE + rr] = p;
                sum += p;
            }
            mrow[rr] = mnew;
            lrow[rr] = lrow[rr] * corr + sum;
            crow[rr] = corr;
        }
        __syncthreads();

        #pragma unroll
        for (int i = 0; i < 4; i++) {
            const float cr = crow[r0 + i];
            #pragma unroll
            for (int j = 0; j < 4; j++) acc[i][j] *= cr;
        }
        {
            const float4* src = (const float4*)(Vb + (size_t)jt * 64 * DH);
            float4* dst = (float4*)KVs;
            #pragma unroll
            for (int rep = 0; rep < 4; rep++) dst[tid + rep * 256] = src[tid + rep * 256];
        }
        __syncthreads();

        #pragma unroll 8
        for (int t = 0; t < 64; t++) {
            float ra[4], rb[4];
            *(float4*)ra = *(const float4*)&SsT[t * SST_STRIDE + r0];
            *(float4*)rb = *(const float4*)&KVs[t * 64 + c0];
            #pragma unroll
            for (int i = 0; i < 4; i++)
                #pragma unroll
                for (int j = 0; j < 4; j++) acc[i][j] += ra[i] * rb[j];
        }
        __syncthreads();
    }

    const int b = bh >> 4;
    const int h = bh & 15;
    #pragma unroll
    for (int i = 0; i < 4; i++) {
        const int rr = r0 + i;
        const float inv = 1.f / lrow[rr];
        const int s = it * 64 + rr;
        float* dst = g_ctx + ((size_t)b * SS + s) * DM + h * 64 + c0;
        float4 v;
        v.x = acc[i][0] * inv; v.y = acc[i][1] * inv;
        v.z = acc[i][2] * inv; v.w = acc[i][3] * inv;
        *(float4*)dst = v;
    }
}

// ============================================================
extern "C" void kernel_launch(void* const* d_in, const int* in_sizes, int n_in,
                              void* d_out, int out_size)
{
    const float* x  = (const float*)d_in[0];
    const float* Wq = (const float*)d_in[1];
    const float* bq = (const float*)d_in[2];
    const float* Wk = (const float*)d_in[3];
    const float* bk = (const float*)d_in[4];
    const float* Wv = (const float*)d_in[5];
    const float* bv = (const float*)d_in[6];
    const float* Wo = (const float*)d_in[7];
    const float* bo = (const float*)d_in[8];
    float* out = (float*)d_out;

    cudaFuncSetAttribute(gemm_tc<0>, cudaFuncAttributeMaxDynamicSharedMemorySize, GEMM_SMEM_BYTES);
    cudaFuncSetAttribute(gemm_tc<1>, cudaFuncAttributeMaxDynamicSharedMemorySize, GEMM_SMEM_BYTES);
    cudaFuncSetAttribute(attn_kernel, cudaFuncAttributeMaxDynamicSharedMemorySize, ATTN_SMEM_BYTES);

    gemm_tc<0><<<dim3(DM / 128, MM / 128, 3), 256, GEMM_SMEM_BYTES>>>(
        x, Wq, bq, Wk, bk, Wv, bv, nullptr);
    attn_kernel<<<dim3(SS / 64, BB * NH), 256, ATTN_SMEM_BYTES>>>();
    gemm_tc<1><<<dim3(DM / 128, MM / 128), 256, GEMM_SMEM_BYTES>>>(
        g_ctx, Wo, bo, nullptr, nullptr, nullptr, nullptr, out);
}

// round 6
// speedup vs baseline: 1.7889x; 1.3082x over previous
#include <cuda_runtime.h>
#include <cuda_bf16.h>
#include <cstdint>
#include <math.h>

// Problem constants
#define BB   2
#define SS   2048
#define DM   1024
#define NH   16
#define DH   64
#define MM   (BB*SS)

// -------- scratch (device globals; allocation-free) --------
__device__ float g_q[BB*NH*SS*DH];    // [b][h][s][d]  (tf32 bits)
__device__ float g_k[BB*NH*SS*DH];    // (tf32 bits)
__device__ float g_v[BB*NH*SS*DH];    // (tf32 bits)
__device__ float g_ctx[MM*DM];        // [b*S+s][h*64+d] fp32

// ============================================================
// helpers
// ============================================================
__device__ __forceinline__ uint32_t smem_u32(const void* p) {
    uint32_t a;
    asm("{ .reg .u64 t; cvta.to.shared.u64 t, %1; cvt.u32.u64 %0, t; }" : "=r"(a) : "l"(p));
    return a;
}
__device__ __forceinline__ uint32_t cvt_tf32(float a) {
    uint32_t r;
    asm("cvt.rna.tf32.f32 %0, %1;" : "=r"(r) : "f"(a));
    return r;
}
__device__ __forceinline__ float ex2_fast(float x) {
    float r;
    asm("ex2.approx.ftz.f32 %0, %1;" : "=f"(r) : "f"(x));
    return r;
}

#define LDSM4(d0, d1, d2, d3, addr)                                            \
    asm volatile("ldmatrix.sync.aligned.m8n8.x4.shared.b16 {%0,%1,%2,%3}, [%4];" \
                 : "=r"(d0), "=r"(d1), "=r"(d2), "=r"(d3) : "r"(addr))

#define MMA16816(c, a0, a1, a2, a3, b0, b1)                                    \
    asm volatile("mma.sync.aligned.m16n8k16.row.col.f32.bf16.bf16.f32 "        \
                 "{%0,%1,%2,%3}, {%4,%5,%6,%7}, {%8,%9}, {%0,%1,%2,%3};"       \
                 : "+f"((c)[0]), "+f"((c)[1]), "+f"((c)[2]), "+f"((c)[3])      \
                 : "r"(a0), "r"(a1), "r"(a2), "r"(a3), "r"(b0), "r"(b1))

#define MMA_TF32(c, a0, a1, a2, a3, b0, b1)                                    \
    asm volatile("mma.sync.aligned.m16n8k8.row.col.f32.tf32.tf32.f32 "         \
                 "{%0,%1,%2,%3}, {%4,%5,%6,%7}, {%8,%9}, {%0,%1,%2,%3};"       \
                 : "+f"((c)[0]), "+f"((c)[1]), "+f"((c)[2]), "+f"((c)[3])      \
                 : "r"(a0), "r"(a1), "r"(a2), "r"(a3), "r"(b0), "r"(b1))

// ============================================================
// bf16-split tensor-core GEMM:  out = A @ W^T + bias  (unchanged core from R5)
// MODE 0: QKV, epilogue scatters to [b][h][s][d] AS TF32 BITS
// MODE 1: output projection, epilogue row-major fp32 to d_out
// ============================================================
#define TILE_B   16384
#define STAGE_B  (4*TILE_B)
#define GEMM_SMEM_BYTES (1024 + 2*STAGE_B)

__device__ __forceinline__ void conv_sts(const float4& u, const float4& v,
                                         char* hi_tile, char* lo_tile,
                                         int r, int chunk_logical)
{
    const int chunk = chunk_logical ^ (r & 7);
    const int off = r * 128 + chunk * 16;
    __nv_bfloat162 h01 = __floats2bfloat162_rn(u.x, u.y);
    __nv_bfloat162 h23 = __floats2bfloat162_rn(u.z, u.w);
    __nv_bfloat162 h45 = __floats2bfloat162_rn(v.x, v.y);
    __nv_bfloat162 h67 = __floats2bfloat162_rn(v.z, v.w);
    uint4 hv = make_uint4(*(uint32_t*)&h01, *(uint32_t*)&h23,
                          *(uint32_t*)&h45, *(uint32_t*)&h67);
    float4 lu, lv;
    lu.x = u.x - __bfloat162float(h01.x); lu.y = u.y - __bfloat162float(h01.y);
    lu.z = u.z - __bfloat162float(h23.x); lu.w = u.w - __bfloat162float(h23.y);
    lv.x = v.x - __bfloat162float(h45.x); lv.y = v.y - __bfloat162float(h45.y);
    lv.z = v.z - __bfloat162float(h67.x); lv.w = v.w - __bfloat162float(h67.y);
    __nv_bfloat162 l01 = __floats2bfloat162_rn(lu.x, lu.y);
    __nv_bfloat162 l23 = __floats2bfloat162_rn(lu.z, lu.w);
    __nv_bfloat162 l45 = __floats2bfloat162_rn(lv.x, lv.y);
    __nv_bfloat162 l67 = __floats2bfloat162_rn(lv.z, lv.w);
    uint4 lw = make_uint4(*(uint32_t*)&l01, *(uint32_t*)&l23,
                          *(uint32_t*)&l45, *(uint32_t*)&l67);
    *(uint4*)(hi_tile + off) = hv;
    *(uint4*)(lo_tile + off) = lw;
}

template<int MODE>
__global__ __launch_bounds__(256, 1) void gemm_tc(
    const float* __restrict__ X,
    const float* __restrict__ W1, const float* __restrict__ b1,
    const float* __restrict__ W2, const float* __restrict__ b2,
    const float* __restrict__ W3, const float* __restrict__ b3,
    float* __restrict__ outp)
{
    extern __shared__ char smraw[];
    char* tiles = (char*)(((uintptr_t)smraw + 1023) & ~(uintptr_t)1023);
    const uint32_t tiles32 = smem_u32(tiles);

    const int tid  = threadIdx.x;
    const int wid  = tid >> 5;
    const int lane = tid & 31;
    const int bm = blockIdx.y * 128;
    const int bn = blockIdx.x * 128;

    const float* A;
    const float* W;
    const float* bias;
    if (MODE == 0) {
        A = X;
        const int z = blockIdx.z;
        W    = (z == 0) ? W1 : (z == 1) ? W2 : W3;
        bias = (z == 0) ? b1 : (z == 1) ? b2 : b3;
    } else {
        A = g_ctx; W = W1; bias = b1;
    }

    const int r    = tid >> 1;
    const int half = tid & 1;
    const float* arow = A + (size_t)(bm + r) * DM + half * 32;
    const float* wrow = W + (size_t)(bn + r) * DM + half * 32;

    const int lrow = (lane & 7) | (((lane >> 3) & 1) << 3);
    const int lkh  = lane >> 4;
    const int r7   = lane & 7;
    const int wm   = (wid >> 2) * 64;
    const int wn   = (wid & 3) * 32;

    float acc[4][4][4];
    #pragma unroll
    for (int i = 0; i < 4; i++)
        #pragma unroll
        for (int j = 0; j < 4; j++)
            #pragma unroll
            for (int c = 0; c < 4; c++) acc[i][j][c] = 0.f;

    float4 pf[8];

    {
        char* st = tiles;
        #pragma unroll
        for (int v = 0; v < 8; v++) pf[v] = ((const float4*)arow)[v];
        #pragma unroll
        for (int g = 0; g < 4; g++)
            conv_sts(pf[2*g], pf[2*g+1], st, st + TILE_B, r, half*4 + g);
        #pragma unroll
        for (int v = 0; v < 8; v++) pf[v] = ((const float4*)wrow)[v];
        #pragma unroll
        for (int g = 0; g < 4; g++)
            conv_sts(pf[2*g], pf[2*g+1], st + 2*TILE_B, st + 3*TILE_B, r, half*4 + g);
    }
    __syncthreads();

    for (int kb = 0; kb < 16; kb++) {
        const int j = kb & 1;
        const uint32_t Ahi = tiles32 + j * STAGE_B;
        const uint32_t Alo = Ahi + TILE_B;
        const uint32_t Bhi = Ahi + 2*TILE_B;
        const uint32_t Blo = Ahi + 3*TILE_B;
        char* nst = tiles + (j ^ 1) * STAGE_B;
        const bool more = (kb < 15);

        if (more) {
            const float* src = arow + (kb + 1) * 64;
            #pragma unroll
            for (int v = 0; v < 8; v++) pf[v] = ((const float4*)src)[v];
        }

        #pragma unroll
        for (int k16 = 0; k16 < 2; k16++) {
            uint32_t ahi[4][4], alo[4][4], bhi[2][4], blo[2][4];
            const int ck = ((2*k16 + lkh) ^ r7) * 16;
            #pragma unroll
            for (int i = 0; i < 4; i++) {
                const uint32_t ro = (uint32_t)(wm + i*16 + lrow) * 128 + ck;
                LDSM4(ahi[i][0], ahi[i][1], ahi[i][2], ahi[i][3], Ahi + ro);
                LDSM4(alo[i][0], alo[i][1], alo[i][2], alo[i][3], Alo + ro);
            }
            #pragma unroll
            for (int p = 0; p < 2; p++) {
                const uint32_t ro = (uint32_t)(wn + p*16 + lrow) * 128 + ck;
                LDSM4(bhi[p][0], bhi[p][1], bhi[p][2], bhi[p][3], Bhi + ro);
                LDSM4(blo[p][0], blo[p][1], blo[p][2], blo[p][3], Blo + ro);
            }
            #pragma unroll
            for (int i = 0; i < 4; i++)
                #pragma unroll
                for (int jn = 0; jn < 4; jn++) {
                    const int p = jn >> 1, q = jn & 1;
                    MMA16816(acc[i][jn], ahi[i][0], ahi[i][1], ahi[i][2], ahi[i][3],
                             bhi[p][q], bhi[p][q+2]);
                    MMA16816(acc[i][jn], ahi[i][0], ahi[i][1], ahi[i][2], ahi[i][3],
                             blo[p][q], blo[p][q+2]);
                    MMA16816(acc[i][jn], alo[i][0], alo[i][1], alo[i][2], alo[i][3],
                             bhi[p][q], bhi[p][q+2]);
                }
        }

        if (more) {
            #pragma unroll
            for (int g = 0; g < 4; g++)
                conv_sts(pf[2*g], pf[2*g+1], nst, nst + TILE_B, r, half*4 + g);
            const float* src = wrow + (kb + 1) * 64;
            #pragma unroll
            for (int v = 0; v < 8; v++) pf[v] = ((const float4*)src)[v];
        }

        #pragma unroll
        for (int k16 = 2; k16 < 4; k16++) {
            uint32_t ahi[4][4], alo[4][4], bhi[2][4], blo[2][4];
            const int ck = ((2*k16 + lkh) ^ r7) * 16;
            #pragma unroll
            for (int i = 0; i < 4; i++) {
                const uint32_t ro = (uint32_t)(wm + i*16 + lrow) * 128 + ck;
                LDSM4(ahi[i][0], ahi[i][1], ahi[i][2], ahi[i][3], Ahi + ro);
                LDSM4(alo[i][0], alo[i][1], alo[i][2], alo[i][3], Alo + ro);
            }
            #pragma unroll
            for (int p = 0; p < 2; p++) {
                const uint32_t ro = (uint32_t)(wn + p*16 + lrow) * 128 + ck;
                LDSM4(bhi[p][0], bhi[p][1], bhi[p][2], bhi[p][3], Bhi + ro);
                LDSM4(blo[p][0], blo[p][1], blo[p][2], blo[p][3], Blo + ro);
            }
            #pragma unroll
            for (int i = 0; i < 4; i++)
                #pragma unroll
                for (int jn = 0; jn < 4; jn++) {
                    const int p = jn >> 1, q = jn & 1;
                    MMA16816(acc[i][jn], ahi[i][0], ahi[i][1], ahi[i][2], ahi[i][3],
                             bhi[p][q], bhi[p][q+2]);
                    MMA16816(acc[i][jn], ahi[i][0], ahi[i][1], ahi[i][2], ahi[i][3],
                             blo[p][q], blo[p][q+2]);
                    MMA16816(acc[i][jn], alo[i][0], alo[i][1], alo[i][2], alo[i][3],
                             bhi[p][q], bhi[p][q+2]);
                }
        }

        if (more) {
            #pragma unroll
            for (int g = 0; g < 4; g++)
                conv_sts(pf[2*g], pf[2*g+1], nst + 2*TILE_B, nst + 3*TILE_B, r, half*4 + g);
        }
        __syncthreads();
    }

    // ---- epilogue ----
    const int qrow = lane >> 2;
    const int qcol = (lane & 3) * 2;
    #pragma unroll
    for (int jn = 0; jn < 4; jn++) {
        const int col = bn + wn + jn*8 + qcol;
        const float bx = bias[col], by = bias[col + 1];
        #pragma unroll
        for (int i = 0; i < 4; i++) {
            const int row0 = bm + wm + i*16 + qrow;
            #pragma unroll
            for (int hh = 0; hh < 2; hh++) {
                const int row = row0 + hh*8;
                float ox = acc[i][jn][2*hh+0] + bx;
                float oy = acc[i][jn][2*hh+1] + by;
                if (MODE == 0) {
                    // store as tf32 bits: attention consumes tf32 operands directly
                    const int z = blockIdx.z;
                    float* out = (z == 0) ? g_q : (z == 1) ? g_k : g_v;
                    const int b = row >> 11;
                    const int s = row & 2047;
                    const int h = col >> 6;
                    const int d = col & 63;
                    float2 o;
                    o.x = __uint_as_float(cvt_tf32(ox));
                    o.y = __uint_as_float(cvt_tf32(oy));
                    *(float2*)(out + ((((size_t)b * NH + h) * SS + s) * DH + d)) = o;
                } else {
                    float2 o = make_float2(ox, oy);
                    *(float2*)(outp + (size_t)row * DM + col) = o;
                }
            }
        }
    }
}

// ============================================================
// Flash attention v2: tf32 mma.sync, causal, online softmax in exp2 domain.
// CTA = 64 q-rows x 64 keys/iter, 128 threads (4 warps, 16 rows each).
// Q held in registers as tf32 A-fragments. K/V/P staged in padded smem.
// ============================================================
#define KSTR 68
#define VSTR 68
#define PSTR 72
#define ATT_SMEM_BYTES ((64*KSTR + 64*VSTR + 64*PSTR) * 4)

__global__ __launch_bounds__(128) void attn_tc()
{
    extern __shared__ float smf[];
    float* Ks = smf;                 // [64][KSTR]
    float* Vs = smf + 64*KSTR;       // [64][VSTR]
    float* Ps = smf + 64*(KSTR+VSTR);// [64][PSTR]

    const int tid  = threadIdx.x;
    const int lane = tid & 31;
    const int wid  = tid >> 5;
    const int it   = (int)gridDim.x - 1 - (int)blockIdx.x;  // heavy tiles first
    const int bh   = blockIdx.y;

    const float* Qb = g_q + (size_t)bh * SS * DH;
    const float* Kb = g_k + (size_t)bh * SS * DH;
    const float* Vb = g_v + (size_t)bh * SS * DH;

    const int qr = lane >> 2;            // 0..7
    const int qc = lane & 3;             // 0..3
    const int row_lo = wid * 16 + qr;    // local q row
    const int row_hi = row_lo + 8;

    // Q fragments (already tf32 bits in gmem)
    uint32_t qf[8][4];
    #pragma unroll
    for (int kk = 0; kk < 8; kk++) {
        const int k0 = kk*8 + qc;
        qf[kk][0] = __float_as_uint(Qb[(size_t)(it*64 + row_lo)*DH + k0]);
        qf[kk][1] = __float_as_uint(Qb[(size_t)(it*64 + row_hi)*DH + k0]);
        qf[kk][2] = __float_as_uint(Qb[(size_t)(it*64 + row_lo)*DH + k0 + 4]);
        qf[kk][3] = __float_as_uint(Qb[(size_t)(it*64 + row_hi)*DH + k0 + 4]);
    }

    const float SC = 0.18033688f;        // (1/8) * log2(e): exp2 domain
    float m0 = -1e30f, m1 = -1e30f, l0 = 0.f, l1 = 0.f;
    float o[8][4];
    #pragma unroll
    for (int nt = 0; nt < 8; nt++)
        #pragma unroll
        for (int c = 0; c < 4; c++) o[nt][c] = 0.f;

    const int lrow = tid >> 1;           // 0..63 (tile fill)
    const int lcol = (tid & 1) * 32;

    for (int jt = 0; jt <= it; jt++) {
        // ---- fill K,V tiles (tf32 bits, straight copy) ----
        {
            const float4* kp = (const float4*)(Kb + (size_t)(jt*64 + lrow)*DH + lcol);
            const float4* vp = (const float4*)(Vb + (size_t)(jt*64 + lrow)*DH + lcol);
            #pragma unroll
            for (int v = 0; v < 8; v++) {
                *(float4*)&Ks[lrow*KSTR + lcol + v*4] = kp[v];
                *(float4*)&Vs[lrow*VSTR + lcol + v*4] = vp[v];
            }
        }
        __syncthreads();

        // ---- S = Q K^T (raw, unscaled) ----
        float s[8][4];
        #pragma unroll
        for (int nt = 0; nt < 8; nt++)
            #pragma unroll
            for (int c = 0; c < 4; c++) s[nt][c] = 0.f;

        #pragma unroll
        for (int kk = 0; kk < 8; kk++) {
            #pragma unroll
            for (int nt = 0; nt < 8; nt++) {
                const uint32_t b0 = __float_as_uint(Ks[(nt*8 + qr)*KSTR + kk*8 + qc]);
                const uint32_t b1 = __float_as_uint(Ks[(nt*8 + qr)*KSTR + kk*8 + qc + 4]);
                MMA_TF32(s[nt], qf[kk][0], qf[kk][1], qf[kk][2], qf[kk][3], b0, b1);
            }
        }

        // ---- causal mask (diag tile only) ----
        if (jt == it) {
            #pragma unroll
            for (int nt = 0; nt < 8; nt++) {
                const int c0 = nt*8 + qc*2;
                if (c0     > row_lo) s[nt][0] = -1e30f;
                if (c0 + 1 > row_lo) s[nt][1] = -1e30f;
                if (c0     > row_hi) s[nt][2] = -1e30f;
                if (c0 + 1 > row_hi) s[nt][3] = -1e30f;
            }
        }

        // ---- online softmax (exp2 domain, scale folded into FFMA) ----
        float tm0 = -1e30f, tm1 = -1e30f;
        #pragma unroll
        for (int nt = 0; nt < 8; nt++) {
            tm0 = fmaxf(tm0, fmaxf(s[nt][0], s[nt][1]));
            tm1 = fmaxf(tm1, fmaxf(s[nt][2], s[nt][3]));
        }
        tm0 = fmaxf(tm0, __shfl_xor_sync(0xffffffffu, tm0, 1));
        tm0 = fmaxf(tm0, __shfl_xor_sync(0xffffffffu, tm0, 2));
        tm1 = fmaxf(tm1, __shfl_xor_sync(0xffffffffu, tm1, 1));
        tm1 = fmaxf(tm1, __shfl_xor_sync(0xffffffffu, tm1, 2));

        const float mn0 = fmaxf(m0, tm0);
        const float mn1 = fmaxf(m1, tm1);
        const float corr0 = ex2_fast((m0 - mn0) * SC);
        const float corr1 = ex2_fast((m1 - mn1) * SC);
        m0 = mn0; m1 = mn1;
        const float nms0 = -mn0 * SC;
        const float nms1 = -mn1 * SC;

        float ls0 = 0.f, ls1 = 0.f;
        #pragma unroll
        for (int nt = 0; nt < 8; nt++) {
            const float p0 = ex2_fast(fmaf(s[nt][0], SC, nms0));
            const float p1 = ex2_fast(fmaf(s[nt][1], SC, nms0));
            const float p2 = ex2_fast(fmaf(s[nt][2], SC, nms1));
            const float p3 = ex2_fast(fmaf(s[nt][3], SC, nms1));
            ls0 += p0 + p1;
            ls1 += p2 + p3;
            uint2 plo = make_uint2(cvt_tf32(p0), cvt_tf32(p1));
            uint2 phi = make_uint2(cvt_tf32(p2), cvt_tf32(p3));
            *(uint2*)&Ps[row_lo*PSTR + nt*8 + qc*2] = plo;
            *(uint2*)&Ps[row_hi*PSTR + nt*8 + qc*2] = phi;
        }
        ls0 += __shfl_xor_sync(0xffffffffu, ls0, 1);
        ls0 += __shfl_xor_sync(0xffffffffu, ls0, 2);
        ls1 += __shfl_xor_sync(0xffffffffu, ls1, 1);
        ls1 += __shfl_xor_sync(0xffffffffu, ls1, 2);
        l0 = l0 * corr0 + ls0;
        l1 = l1 * corr1 + ls1;

        #pragma unroll
        for (int nt = 0; nt < 8; nt++) {
            o[nt][0] *= corr0; o[nt][1] *= corr0;
            o[nt][2] *= corr1; o[nt][3] *= corr1;
        }
        __syncwarp();   // P produced & consumed within the same warp's rows

        // ---- O += P V ----
        #pragma unroll
        for (int kt = 0; kt < 8; kt++) {
            const uint32_t a0 = __float_as_uint(Ps[row_lo*PSTR + kt*8 + qc]);
            const uint32_t a1 = __float_as_uint(Ps[row_hi*PSTR + kt*8 + qc]);
            const uint32_t a2 = __float_as_uint(Ps[row_lo*PSTR + kt*8 + qc + 4]);
            const uint32_t a3 = __float_as_uint(Ps[row_hi*PSTR + kt*8 + qc + 4]);
            #pragma unroll
            for (int nt = 0; nt < 8; nt++) {
                const uint32_t b0 = __float_as_uint(Vs[(kt*8 + qc)*VSTR + nt*8 + qr]);
                const uint32_t b1 = __float_as_uint(Vs[(kt*8 + qc + 4)*VSTR + nt*8 + qr]);
                MMA_TF32(o[nt], a0, a1, a2, a3, b0, b1);
            }
        }
        __syncthreads();  // all K/V/P reads done before next tile overwrites
    }

    // ---- epilogue: normalize, write g_ctx fp32 ----
    const int b = bh >> 4;
    const int h = bh & 15;
    const float i0 = 1.f / l0;
    const float i1 = 1.f / l1;
    const int s0g = it*64 + row_lo;
    const int s1g = it*64 + row_hi;
    #pragma unroll
    for (int nt = 0; nt < 8; nt++) {
        const int d = h*64 + nt*8 + qc*2;
        float2 w0 = make_float2(o[nt][0] * i0, o[nt][1] * i0);
        float2 w1 = make_float2(o[nt][2] * i1, o[nt][3] * i1);
        *(float2*)&g_ctx[(size_t)(b*SS + s0g)*DM + d] = w0;
        *(float2*)&g_ctx[(size_t)(b*SS + s1g)*DM + d] = w1;
    }
}

// ============================================================
extern "C" void kernel_launch(void* const* d_in, const int* in_sizes, int n_in,
                              void* d_out, int out_size)
{
    const float* x  = (const float*)d_in[0];
    const float* Wq = (const float*)d_in[1];
    const float* bq = (const float*)d_in[2];
    const float* Wk = (const float*)d_in[3];
    const float* bk = (const float*)d_in[4];
    const float* Wv = (const float*)d_in[5];
    const float* bv = (const float*)d_in[6];
    const float* Wo = (const float*)d_in[7];
    const float* bo = (const float*)d_in[8];
    float* out = (float*)d_out;

    cudaFuncSetAttribute(gemm_tc<0>, cudaFuncAttributeMaxDynamicSharedMemorySize, GEMM_SMEM_BYTES);
    cudaFuncSetAttribute(gemm_tc<1>, cudaFuncAttributeMaxDynamicSharedMemorySize, GEMM_SMEM_BYTES);
    cudaFuncSetAttribute(attn_tc, cudaFuncAttributeMaxDynamicSharedMemorySize, ATT_SMEM_BYTES);

    gemm_tc<0><<<dim3(DM / 128, MM / 128, 3), 256, GEMM_SMEM_BYTES>>>(
        x, Wq, bq, Wk, bk, Wv, bv, nullptr);
    attn_tc<<<dim3(SS / 64, BB * NH), 128, ATT_SMEM_BYTES>>>();
    gemm_tc<1><<<dim3(DM / 128, MM / 128), 256, GEMM_SMEM_BYTES>>>(
        g_ctx, Wo, bo, nullptr, nullptr, nullptr, nullptr, out);
}

// round 10
// speedup vs baseline: 2.1097x; 1.1794x over previous
#include <cuda_runtime.h>
#include <cuda_bf16.h>
#include <cstdint>
#include <math.h>

// Problem constants
#define BB   2
#define SS   2048
#define DM   1024
#define NH   16
#define DH   64
#define MM   (BB*SS)

// -------- scratch (device globals; allocation-free) --------
__device__ float g_q[BB*NH*SS*DH];    // [b][h][s][d]  (tf32 bits)
__device__ float g_k[BB*NH*SS*DH];    // (tf32 bits)
__device__ float g_v[BB*NH*SS*DH];    // (tf32 bits)
__device__ float g_ctx[MM*DM];        // [b*S+s][h*64+d] fp32

// ============================================================
// helpers
// ============================================================
__device__ __forceinline__ uint32_t smem_u32(const void* p) {
    uint32_t a;
    asm("{ .reg .u64 t; cvta.to.shared.u64 t, %1; cvt.u32.u64 %0, t; }" : "=r"(a) : "l"(p));
    return a;
}
__device__ __forceinline__ uint32_t cvt_tf32(float a) {
    uint32_t r;
    asm("cvt.rna.tf32.f32 %0, %1;" : "=r"(r) : "f"(a));
    return r;
}
__device__ __forceinline__ float ex2_fast(float x) {
    float r;
    asm("ex2.approx.ftz.f32 %0, %1;" : "=f"(r) : "f"(x));
    return r;
}

#define LDSM4(d0, d1, d2, d3, addr)                                            \
    asm volatile("ldmatrix.sync.aligned.m8n8.x4.shared.b16 {%0,%1,%2,%3}, [%4];" \
                 : "=r"(d0), "=r"(d1), "=r"(d2), "=r"(d3) : "r"(addr))

#define MMA16816(c, a0, a1, a2, a3, b0, b1)                                    \
    asm volatile("mma.sync.aligned.m16n8k16.row.col.f32.bf16.bf16.f32 "        \
                 "{%0,%1,%2,%3}, {%4,%5,%6,%7}, {%8,%9}, {%0,%1,%2,%3};"       \
                 : "+f"((c)[0]), "+f"((c)[1]), "+f"((c)[2]), "+f"((c)[3])      \
                 : "r"(a0), "r"(a1), "r"(a2), "r"(a3), "r"(b0), "r"(b1))

#define MMA_TF32(c, a0, a1, a2, a3, b0, b1)                                    \
    asm volatile("mma.sync.aligned.m16n8k8.row.col.f32.tf32.tf32.f32 "         \
                 "{%0,%1,%2,%3}, {%4,%5,%6,%7}, {%8,%9}, {%0,%1,%2,%3};"       \
                 : "+f"((c)[0]), "+f"((c)[1]), "+f"((c)[2]), "+f"((c)[3])      \
                 : "r"(a0), "r"(a1), "r"(a2), "r"(a3), "r"(b0), "r"(b1))

// ============================================================
// bf16-split tensor-core GEMM:  out = A @ W^T + bias
// CTA 128x128, BK=64, NOW 512 threads = 16 warps in 4x4 grid (warp tile 32x32)
// for 4 warps/SMSP latency hiding (R6: issue was 24% with 2 warps/SMSP).
// SMEM per stage: Ahi/Alo/Bhi/Blo 128x64 bf16, swizzled 128B rows.
// MODE 0: QKV (blockIdx.z selects), epilogue scatters to [b][h][s][d] tf32 bits
// MODE 1: output projection, epilogue row-major fp32 to d_out
// ============================================================
#define TILE_B   16384
#define STAGE_B  (4*TILE_B)
#define GEMM_SMEM_BYTES (1024 + 2*STAGE_B)

__device__ __forceinline__ void conv_sts(const float4& u, const float4& v,
                                         char* hi_tile, char* lo_tile,
                                         int r, int chunk_logical)
{
    const int chunk = chunk_logical ^ (r & 7);
    const int off = r * 128 + chunk * 16;
    __nv_bfloat162 h01 = __floats2bfloat162_rn(u.x, u.y);
    __nv_bfloat162 h23 = __floats2bfloat162_rn(u.z, u.w);
    __nv_bfloat162 h45 = __floats2bfloat162_rn(v.x, v.y);
    __nv_bfloat162 h67 = __floats2bfloat162_rn(v.z, v.w);
    uint4 hv = make_uint4(*(uint32_t*)&h01, *(uint32_t*)&h23,
                          *(uint32_t*)&h45, *(uint32_t*)&h67);
    float4 lu, lv;
    lu.x = u.x - __bfloat162float(h01.x); lu.y = u.y - __bfloat162float(h01.y);
    lu.z = u.z - __bfloat162float(h23.x); lu.w = u.w - __bfloat162float(h23.y);
    lv.x = v.x - __bfloat162float(h45.x); lv.y = v.y - __bfloat162float(h45.y);
    lv.z = v.z - __bfloat162float(h67.x); lv.w = v.w - __bfloat162float(h67.y);
    __nv_bfloat162 l01 = __floats2bfloat162_rn(lu.x, lu.y);
    __nv_bfloat162 l23 = __floats2bfloat162_rn(lu.z, lu.w);
    __nv_bfloat162 l45 = __floats2bfloat162_rn(lv.x, lv.y);
    __nv_bfloat162 l67 = __floats2bfloat162_rn(lv.z, lv.w);
    uint4 lw = make_uint4(*(uint32_t*)&l01, *(uint32_t*)&l23,
                          *(uint32_t*)&l45, *(uint32_t*)&l67);
    *(uint4*)(hi_tile + off) = hv;
    *(uint4*)(lo_tile + off) = lw;
}

template<int MODE>
__global__ __launch_bounds__(512, 1) void gemm_tc(
    const float* __restrict__ X,
    const float* __restrict__ W1, const float* __restrict__ b1,
    const float* __restrict__ W2, const float* __restrict__ b2,
    const float* __restrict__ W3, const float* __restrict__ b3,
    float* __restrict__ outp)
{
    extern __shared__ char smraw[];
    char* tiles = (char*)(((uintptr_t)smraw + 1023) & ~(uintptr_t)1023);
    const uint32_t tiles32 = smem_u32(tiles);

    const int tid  = threadIdx.x;
    const int wid  = tid >> 5;
    const int lane = tid & 31;
    const int bm = blockIdx.y * 128;
    const int bn = blockIdx.x * 128;

    const float* A;
    const float* W;
    const float* bias;
    if (MODE == 0) {
        A = X;
        const int z = blockIdx.z;
        W    = (z == 0) ? W1 : (z == 1) ? W2 : W3;
        bias = (z == 0) ? b1 : (z == 1) ? b2 : b3;
    } else {
        A = g_ctx; W = W1; bias = b1;
    }

    // fill indexing: 4 threads per row, 16 floats each
    const int r  = tid >> 2;            // 0..127
    const int qt = tid & 3;             // quarter: 16-float chunk
    const float* arow = A + (size_t)(bm + r) * DM + qt * 16;
    const float* wrow = W + (size_t)(bn + r) * DM + qt * 16;

    // ldmatrix lane addressing
    const int lrow = (lane & 7) | (((lane >> 3) & 1) << 3);  // 0..15
    const int lkh  = lane >> 4;                              // k half 0/1
    const int r7   = lane & 7;
    const int wm   = (wid >> 2) * 32;    // warp m offset
    const int wn   = (wid & 3) * 32;     // warp n offset

    float acc[2][4][4];
    #pragma unroll
    for (int i = 0; i < 2; i++)
        #pragma unroll
        for (int j = 0; j < 4; j++)
            #pragma unroll
            for (int c = 0; c < 4; c++) acc[i][j][c] = 0.f;

    float4 pf[4];

    // ---- prologue: fill stage 0 ----
    {
        char* st = tiles;
        #pragma unroll
        for (int v = 0; v < 4; v++) pf[v] = ((const float4*)arow)[v];
        conv_sts(pf[0], pf[1], st, st + TILE_B, r, qt*2 + 0);
        conv_sts(pf[2], pf[3], st, st + TILE_B, r, qt*2 + 1);
        #pragma unroll
        for (int v = 0; v < 4; v++) pf[v] = ((const float4*)wrow)[v];
        conv_sts(pf[0], pf[1], st + 2*TILE_B, st + 3*TILE_B, r, qt*2 + 0);
        conv_sts(pf[2], pf[3], st + 2*TILE_B, st + 3*TILE_B, r, qt*2 + 1);
    }
    __syncthreads();

    for (int kb = 0; kb < 16; kb++) {
        const int j = kb & 1;
        const uint32_t Ahi = tiles32 + j * STAGE_B;
        const uint32_t Alo = Ahi + TILE_B;
        const uint32_t Bhi = Ahi + 2*TILE_B;
        const uint32_t Blo = Ahi + 3*TILE_B;
        char* nst = tiles + (j ^ 1) * STAGE_B;
        const bool more = (kb < 15);

        // prefetch next A
        if (more) {
            const float* src = arow + (kb + 1) * 64;
            #pragma unroll
            for (int v = 0; v < 4; v++) pf[v] = ((const float4*)src)[v];
        }

        // compute k16 = 0,1
        #pragma unroll
        for (int k16 = 0; k16 < 2; k16++) {
            uint32_t ahi[2][4], alo[2][4], bhi[2][4], blo[2][4];
            const int ck = ((2*k16 + lkh) ^ r7) * 16;
            #pragma unroll
            for (int i = 0; i < 2; i++) {
                const uint32_t ro = (uint32_t)(wm + i*16 + lrow) * 128 + ck;
                LDSM4(ahi[i][0], ahi[i][1], ahi[i][2], ahi[i][3], Ahi + ro);
                LDSM4(alo[i][0], alo[i][1], alo[i][2], alo[i][3], Alo + ro);
            }
            #pragma unroll
            for (int p = 0; p < 2; p++) {
                const uint32_t ro = (uint32_t)(wn + p*16 + lrow) * 128 + ck;
                LDSM4(bhi[p][0], bhi[p][1], bhi[p][2], bhi[p][3], Bhi + ro);
                LDSM4(blo[p][0], blo[p][1], blo[p][2], blo[p][3], Blo + ro);
            }
            #pragma unroll
            for (int i = 0; i < 2; i++)
                #pragma unroll
                for (int jn = 0; jn < 4; jn++) {
                    const int p = jn >> 1, q = jn & 1;
                    MMA16816(acc[i][jn], ahi[i][0], ahi[i][1], ahi[i][2], ahi[i][3],
                             bhi[p][q], bhi[p][q+2]);
                    MMA16816(acc[i][jn], ahi[i][0], ahi[i][1], ahi[i][2], ahi[i][3],
                             blo[p][q], blo[p][q+2]);
                    MMA16816(acc[i][jn], alo[i][0], alo[i][1], alo[i][2], alo[i][3],
                             bhi[p][q], bhi[p][q+2]);
                }
        }

        // store next A, prefetch next B
        if (more) {
            conv_sts(pf[0], pf[1], nst, nst + TILE_B, r, qt*2 + 0);
            conv_sts(pf[2], pf[3], nst, nst + TILE_B, r, qt*2 + 1);
            const float* src = wrow + (kb + 1) * 64;
            #pragma unroll
            for (int v = 0; v < 4; v++) pf[v] = ((const float4*)src)[v];
        }

        // compute k16 = 2,3
        #pragma unroll
        for (int k16 = 2; k16 < 4; k16++) {
            uint32_t ahi[2][4], alo[2][4], bhi[2][4], blo[2][4];
            const int ck = ((2*k16 + lkh) ^ r7) * 16;
            #pragma unroll
            for (int i = 0; i < 2; i++) {
                const uint32_t ro = (uint32_t)(wm + i*16 + lrow) * 128 + ck;
                LDSM4(ahi[i][0], ahi[i][1], ahi[i][2], ahi[i][3], Ahi + ro);
                LDSM4(alo[i][0], alo[i][1], alo[i][2], alo[i][3], Alo + ro);
            }
            #pragma unroll
            for (int p = 0; p < 2; p++) {
                const uint32_t ro = (uint32_t)(wn + p*16 + lrow) * 128 + ck;
                LDSM4(bhi[p][0], bhi[p][1], bhi[p][2], bhi[p][3], Bhi + ro);
                LDSM4(blo[p][0], blo[p][1], blo[p][2], blo[p][3], Blo + ro);
            }
            #pragma unroll
            for (int i = 0; i < 2; i++)
                #pragma unroll
                for (int jn = 0; jn < 4; jn++) {
                    const int p = jn >> 1, q = jn & 1;
                    MMA16816(acc[i][jn], ahi[i][0], ahi[i][1], ahi[i][2], ahi[i][3],
                             bhi[p][q], bhi[p][q+2]);
                    MMA16816(acc[i][jn], ahi[i][0], ahi[i][1], ahi[i][2], ahi[i][3],
                             blo[p][q], blo[p][q+2]);
                    MMA16816(acc[i][jn], alo[i][0], alo[i][1], alo[i][2], alo[i][3],
                             bhi[p][q], bhi[p][q+2]);
                }
        }

        // store next B
        if (more) {
            conv_sts(pf[0], pf[1], nst + 2*TILE_B, nst + 3*TILE_B, r, qt*2 + 0);
            conv_sts(pf[2], pf[3], nst + 2*TILE_B, nst + 3*TILE_B, r, qt*2 + 1);
        }
        __syncthreads();
    }

    // ---- epilogue: D-fragment scatter + bias ----
    const int qrow = lane >> 2;          // 0..7
    const int qcol = (lane & 3) * 2;     // 0,2,4,6
    #pragma unroll
    for (int jn = 0; jn < 4; jn++) {
        const int col = bn + wn + jn*8 + qcol;
        const float bx = bias[col], by = bias[col + 1];
        #pragma unroll
        for (int i = 0; i < 2; i++) {
            const int row0 = bm + wm + i*16 + qrow;
            #pragma unroll
            for (int hh = 0; hh < 2; hh++) {
                const int row = row0 + hh*8;
                float ox = acc[i][jn][2*hh+0] + bx;
                float oy = acc[i][jn][2*hh+1] + by;
                if (MODE == 0) {
                    const int z = blockIdx.z;
                    float* out = (z == 0) ? g_q : (z == 1) ? g_k : g_v;
                    const int b = row >> 11;
                    const int s = row & 2047;
                    const int h = col >> 6;
                    const int d = col & 63;
                    float2 o;
                    o.x = __uint_as_float(cvt_tf32(ox));
                    o.y = __uint_as_float(cvt_tf32(oy));
                    *(float2*)(out + ((((size_t)b * NH + h) * SS + s) * DH + d)) = o;
                } else {
                    float2 o = make_float2(ox, oy);
                    *(float2*)(outp + (size_t)row * DM + col) = o;
                }
            }
        }
    }
}

// ============================================================
// Flash attention: tf32 mma.sync, causal, online softmax in exp2 domain.
// (unchanged — verified in round 6; near MUFU ex2 floor)
// ============================================================
#define KSTR 68
#define VSTR 68
#define PSTR 72
#define ATT_SMEM_BYTES ((64*KSTR + 64*VSTR + 64*PSTR) * 4)

__global__ __launch_bounds__(128) void attn_tc()
{
    extern __shared__ float smf[];
    float* Ks = smf;
    float* Vs = smf + 64*KSTR;
    float* Ps = smf + 64*(KSTR+VSTR);

    const int tid  = threadIdx.x;
    const int lane = tid & 31;
    const int wid  = tid >> 5;
    const int it   = (int)gridDim.x - 1 - (int)blockIdx.x;
    const int bh   = blockIdx.y;

    const float* Qb = g_q + (size_t)bh * SS * DH;
    const float* Kb = g_k + (size_t)bh * SS * DH;
    const float* Vb = g_v + (size_t)bh * SS * DH;

    const int qr = lane >> 2;
    const int qc = lane & 3;
    const int row_lo = wid * 16 + qr;
    const int row_hi = row_lo + 8;

    uint32_t qf[8][4];
    #pragma unroll
    for (int kk = 0; kk < 8; kk++) {
        const int k0 = kk*8 + qc;
        qf[kk][0] = __float_as_uint(Qb[(size_t)(it*64 + row_lo)*DH + k0]);
        qf[kk][1] = __float_as_uint(Qb[(size_t)(it*64 + row_hi)*DH + k0]);
        qf[kk][2] = __float_as_uint(Qb[(size_t)(it*64 + row_lo)*DH + k0 + 4]);
        qf[kk][3] = __float_as_uint(Qb[(size_t)(it*64 + row_hi)*DH + k0 + 4]);
    }

    const float SC = 0.18033688f;        // (1/8) * log2(e)
    float m0 = -1e30f, m1 = -1e30f, l0 = 0.f, l1 = 0.f;
    float o[8][4];
    #pragma unroll
    for (int nt = 0; nt < 8; nt++)
        #pragma unroll
        for (int c = 0; c < 4; c++) o[nt][c] = 0.f;

    const int lrow = tid >> 1;
    const int lcol = (tid & 1) * 32;

    for (int jt = 0; jt <= it; jt++) {
        {
            const float4* kp = (const float4*)(Kb + (size_t)(jt*64 + lrow)*DH + lcol);
            const float4* vp = (const float4*)(Vb + (size_t)(jt*64 + lrow)*DH + lcol);
            #pragma unroll
            for (int v = 0; v < 8; v++) {
                *(float4*)&Ks[lrow*KSTR + lcol + v*4] = kp[v];
                *(float4*)&Vs[lrow*VSTR + lcol + v*4] = vp[v];
            }
        }
        __syncthreads();

        float s[8][4];
        #pragma unroll
        for (int nt = 0; nt < 8; nt++)
            #pragma unroll
            for (int c = 0; c < 4; c++) s[nt][c] = 0.f;

        #pragma unroll
        for (int kk = 0; kk < 8; kk++) {
            #pragma unroll
            for (int nt = 0; nt < 8; nt++) {
                const uint32_t b0 = __float_as_uint(Ks[(nt*8 + qr)*KSTR + kk*8 + qc]);
                const uint32_t b1 = __float_as_uint(Ks[(nt*8 + qr)*KSTR + kk*8 + qc + 4]);
                MMA_TF32(s[nt], qf[kk][0], qf[kk][1], qf[kk][2], qf[kk][3], b0, b1);
            }
        }

        if (jt == it) {
            #pragma unroll
            for (int nt = 0; nt < 8; nt++) {
                const int c0 = nt*8 + qc*2;
                if (c0     > row_lo) s[nt][0] = -1e30f;
                if (c0 + 1 > row_lo) s[nt][1] = -1e30f;
                if (c0     > row_hi) s[nt][2] = -1e30f;
                if (c0 + 1 > row_hi) s[nt][3] = -1e30f;
            }
        }

        float tm0 = -1e30f, tm1 = -1e30f;
        #pragma unroll
        for (int nt = 0; nt < 8; nt++) {
            tm0 = fmaxf(tm0, fmaxf(s[nt][0], s[nt][1]));
            tm1 = fmaxf(tm1, fmaxf(s[nt][2], s[nt][3]));
        }
        tm0 = fmaxf(tm0, __shfl_xor_sync(0xffffffffu, tm0, 1));
        tm0 = fmaxf(tm0, __shfl_xor_sync(0xffffffffu, tm0, 2));
        tm1 = fmaxf(tm1, __shfl_xor_sync(0xffffffffu, tm1, 1));
        tm1 = fmaxf(tm1, __shfl_xor_sync(0xffffffffu, tm1, 2));

        const float mn0 = fmaxf(m0, tm0);
        const float mn1 = fmaxf(m1, tm1);
        const float corr0 = ex2_fast((m0 - mn0) * SC);
        const float corr1 = ex2_fast((m1 - mn1) * SC);
        m0 = mn0; m1 = mn1;
        const float nms0 = -mn0 * SC;
        const float nms1 = -mn1 * SC;

        float ls0 = 0.f, ls1 = 0.f;
        #pragma unroll
        for (int nt = 0; nt < 8; nt++) {
            const float p0 = ex2_fast(fmaf(s[nt][0], SC, nms0));
            const float p1 = ex2_fast(fmaf(s[nt][1], SC, nms0));
            const float p2 = ex2_fast(fmaf(s[nt][2], SC, nms1));
            const float p3 = ex2_fast(fmaf(s[nt][3], SC, nms1));
            ls0 += p0 + p1;
            ls1 += p2 + p3;
            uint2 plo = make_uint2(cvt_tf32(p0), cvt_tf32(p1));
            uint2 phi = make_uint2(cvt_tf32(p2), cvt_tf32(p3));
            *(uint2*)&Ps[row_lo*PSTR + nt*8 + qc*2] = plo;
            *(uint2*)&Ps[row_hi*PSTR + nt*8 + qc*2] = phi;
        }
        ls0 += __shfl_xor_sync(0xffffffffu, ls0, 1);
        ls0 += __shfl_xor_sync(0xffffffffu, ls0, 2);
        ls1 += __shfl_xor_sync(0xffffffffu, ls1, 1);
        ls1 += __shfl_xor_sync(0xffffffffu, ls1, 2);
        l0 = l0 * corr0 + ls0;
        l1 = l1 * corr1 + ls1;

        #pragma unroll
        for (int nt = 0; nt < 8; nt++) {
            o[nt][0] *= corr0; o[nt][1] *= corr0;
            o[nt][2] *= corr1; o[nt][3] *= corr1;
        }
        __syncwarp();

        #pragma unroll
        for (int kt = 0; kt < 8; kt++) {
            const uint32_t a0 = __float_as_uint(Ps[row_lo*PSTR + kt*8 + qc]);
            const uint32_t a1 = __float_as_uint(Ps[row_hi*PSTR + kt*8 + qc]);
            const uint32_t a2 = __float_as_uint(Ps[row_lo*PSTR + kt*8 + qc + 4]);
            const uint32_t a3 = __float_as_uint(Ps[row_hi*PSTR + kt*8 + qc + 4]);
            #pragma unroll
            for (int nt = 0; nt < 8; nt++) {
                const uint32_t b0 = __float_as_uint(Vs[(kt*8 + qc)*VSTR + nt*8 + qr]);
                const uint32_t b1 = __float_as_uint(Vs[(kt*8 + qc + 4)*VSTR + nt*8 + qr]);
                MMA_TF32(o[nt], a0, a1, a2, a3, b0, b1);
            }
        }
        __syncthreads();
    }

    const int b = bh >> 4;
    const int h = bh & 15;
    const float i0 = 1.f / l0;
    const float i1 = 1.f / l1;
    const int s0g = it*64 + row_lo;
    const int s1g = it*64 + row_hi;
    #pragma unroll
    for (int nt = 0; nt < 8; nt++) {
        const int d = h*64 + nt*8 + qc*2;
        float2 w0 = make_float2(o[nt][0] * i0, o[nt][1] * i0);
        float2 w1 = make_float2(o[nt][2] * i1, o[nt][3] * i1);
        *(float2*)&g_ctx[(size_t)(b*SS + s0g)*DM + d] = w0;
        *(float2*)&g_ctx[(size_t)(b*SS + s1g)*DM + d] = w1;
    }
}

// ============================================================
extern "C" void kernel_launch(void* const* d_in, const int* in_sizes, int n_in,
                              void* d_out, int out_size)
{
    const float* x  = (const float*)d_in[0];
    const float* Wq = (const float*)d_in[1];
    const float* bq = (const float*)d_in[2];
    const float* Wk = (const float*)d_in[3];
    const float* bk = (const float*)d_in[4];
    const float* Wv = (const float*)d_in[5];
    const float* bv = (const float*)d_in[6];
    const float* Wo = (const float*)d_in[7];
    const float* bo = (const float*)d_in[8];
    float* out = (float*)d_out;

    cudaFuncSetAttribute(gemm_tc<0>, cudaFuncAttributeMaxDynamicSharedMemorySize, GEMM_SMEM_BYTES);
    cudaFuncSetAttribute(gemm_tc<1>, cudaFuncAttributeMaxDynamicSharedMemorySize, GEMM_SMEM_BYTES);
    cudaFuncSetAttribute(attn_tc, cudaFuncAttributeMaxDynamicSharedMemorySize, ATT_SMEM_BYTES);

    gemm_tc<0><<<dim3(DM / 128, MM / 128, 3), 512, GEMM_SMEM_BYTES>>>(
        x, Wq, bq, Wk, bk, Wv, bv, nullptr);
    attn_tc<<<dim3(SS / 64, BB * NH), 128, ATT_SMEM_BYTES>>>();
    gemm_tc<1><<<dim3(DM / 128, MM / 128), 512, GEMM_SMEM_BYTES>>>(
        g_ctx, Wo, bo, nullptr, nullptr, nullptr, nullptr, out);
}

// round 12
// speedup vs baseline: 2.2815x; 1.0814x over previous
#include <cuda_runtime.h>
#include <cuda_bf16.h>
#include <cstdint>
#include <math.h>

// Problem constants
#define BB   2
#define SS   2048
#define DM   1024
#define NH   16
#define DH   64
#define MM   (BB*SS)

// -------- scratch (device globals; allocation-free) --------
__device__ float g_q[BB*NH*SS*DH];                       // [b][h][s][d] tf32 bits
__device__ float g_k[BB*NH*SS*DH];
__device__ float g_v[BB*NH*SS*DH];
__device__ __align__(16) __nv_bfloat16 g_xhi[MM*DM];     // X split
__device__ __align__(16) __nv_bfloat16 g_xlo[MM*DM];
__device__ __align__(16) __nv_bfloat16 g_whi[3*DM*DM];   // Wq,Wk,Wv split
__device__ __align__(16) __nv_bfloat16 g_wlo[3*DM*DM];
__device__ __align__(16) __nv_bfloat16 g_wohi[DM*DM];    // Wo split
__device__ __align__(16) __nv_bfloat16 g_wolo[DM*DM];
__device__ __align__(16) __nv_bfloat16 g_chi[MM*DM];     // ctx split (attention out)
__device__ __align__(16) __nv_bfloat16 g_clo[MM*DM];

// ============================================================
// helpers
// ============================================================
__device__ __forceinline__ uint32_t smem_u32(const void* p) {
    uint32_t a;
    asm("{ .reg .u64 t; cvta.to.shared.u64 t, %1; cvt.u32.u64 %0, t; }" : "=r"(a) : "l"(p));
    return a;
}
__device__ __forceinline__ uint32_t cvt_tf32(float a) {
    uint32_t r;
    asm("cvt.rna.tf32.f32 %0, %1;" : "=r"(r) : "f"(a));
    return r;
}
__device__ __forceinline__ float ex2_fast(float x) {
    float r;
    asm("ex2.approx.ftz.f32 %0, %1;" : "=f"(r) : "f"(x));
    return r;
}
__device__ __forceinline__ void cp16(uint32_t dst_smem, const void* src) {
    uint64_t g;
    asm("cvta.to.global.u64 %0, %1;" : "=l"(g) : "l"(src));
    asm volatile("cp.async.cg.shared.global [%0], [%1], 16;" :: "r"(dst_smem), "l"(g));
}
#define CP_COMMIT() asm volatile("cp.async.commit_group;" ::: "memory")

#define LDSM4(d0, d1, d2, d3, addr)                                            \
    asm volatile("ldmatrix.sync.aligned.m8n8.x4.shared.b16 {%0,%1,%2,%3}, [%4];" \
                 : "=r"(d0), "=r"(d1), "=r"(d2), "=r"(d3) : "r"(addr))

#define MMA16816(c, a0, a1, a2, a3, b0, b1)                                    \
    asm volatile("mma.sync.aligned.m16n8k16.row.col.f32.bf16.bf16.f32 "        \
                 "{%0,%1,%2,%3}, {%4,%5,%6,%7}, {%8,%9}, {%0,%1,%2,%3};"       \
                 : "+f"((c)[0]), "+f"((c)[1]), "+f"((c)[2]), "+f"((c)[3])      \
                 : "r"(a0), "r"(a1), "r"(a2), "r"(a3), "r"(b0), "r"(b1))

#define MMA_TF32(c, a0, a1, a2, a3, b0, b1)                                    \
    asm volatile("mma.sync.aligned.m16n8k8.row.col.f32.tf32.tf32.f32 "         \
                 "{%0,%1,%2,%3}, {%4,%5,%6,%7}, {%8,%9}, {%0,%1,%2,%3};"       \
                 : "+f"((c)[0]), "+f"((c)[1]), "+f"((c)[2]), "+f"((c)[3])      \
                 : "r"(a0), "r"(a1), "r"(a2), "r"(a3), "r"(b0), "r"(b1))

// ============================================================
// Pre-pass: split fp32 tensors into bf16 hi/lo (once per launch).
// grid = (4096, 5): z selects tensor; x covers elements/4.
// ============================================================
__global__ __launch_bounds__(256) void prep_split(
    const float* __restrict__ x,
    const float* __restrict__ wq, const float* __restrict__ wk,
    const float* __restrict__ wv, const float* __restrict__ wo)
{
    const int z = blockIdx.y;
    const float* src;
    __nv_bfloat16* hi;
    __nv_bfloat16* lo;
    int n4;
    if (z == 0)      { src = x;  hi = g_xhi;             lo = g_xlo;             n4 = MM*DM/4; }
    else if (z == 1) { src = wq; hi = g_whi;             lo = g_wlo;             n4 = DM*DM/4; }
    else if (z == 2) { src = wk; hi = g_whi + DM*DM;     lo = g_wlo + DM*DM;     n4 = DM*DM/4; }
    else if (z == 3) { src = wv; hi = g_whi + 2*DM*DM;   lo = g_wlo + 2*DM*DM;   n4 = DM*DM/4; }
    else             { src = wo; hi = g_wohi;            lo = g_wolo;            n4 = DM*DM/4; }

    const int idx = blockIdx.x * 256 + threadIdx.x;
    if (idx >= n4) return;
    float4 v = ((const float4*)src)[idx];
    __nv_bfloat162 h01 = __floats2bfloat162_rn(v.x, v.y);
    __nv_bfloat162 h23 = __floats2bfloat162_rn(v.z, v.w);
    __nv_bfloat162 l01 = __floats2bfloat162_rn(v.x - __bfloat162float(h01.x),
                                               v.y - __bfloat162float(h01.y));
    __nv_bfloat162 l23 = __floats2bfloat162_rn(v.z - __bfloat162float(h23.x),
                                               v.w - __bfloat162float(h23.y));
    ((__nv_bfloat162*)hi)[2*idx]   = h01;
    ((__nv_bfloat162*)hi)[2*idx+1] = h23;
    ((__nv_bfloat162*)lo)[2*idx]   = l01;
    ((__nv_bfloat162*)lo)[2*idx+1] = l23;
}

// ============================================================
// bf16-split tensor-core GEMM, pre-converted inputs, cp.async 3-stage.
// CTA 128x128, BK=64, 512 threads (16 warps, 4x4, warp tile 32x32).
// SMEM stage: Ahi/Alo/Bhi/Blo 128x64 bf16 (16KB each, 64KB/stage), 3 stages.
// MODE 0: QKV (blockIdx.z), epilogue scatters tf32 bits to g_q/g_k/g_v
// MODE 1: output projection, epilogue fp32 row-major to d_out
// ============================================================
#define TILE_B   16384
#define STAGE_B  (4*TILE_B)
#define STAGES   3
#define GEMM_SMEM_BYTES (1024 + STAGES*STAGE_B)

// issue one stage's cp.async (8 x 16B per thread)
__device__ __forceinline__ void issue_stage(
    const __nv_bfloat16* __restrict__ Ah, const __nv_bfloat16* __restrict__ Al,
    const __nv_bfloat16* __restrict__ Bh, const __nv_bfloat16* __restrict__ Bl,
    uint32_t st, int tid, int kb, int bm, int bn)
{
    #pragma unroll
    for (int t = 0; t < 2; t++) {
        const int id = tid + t * 512;
        const int r  = id >> 3;
        const int c  = id & 7;
        const uint32_t sw = (uint32_t)(r * 128 + ((c ^ (r & 7)) << 4));
        const size_t ga = (size_t)(bm + r) * DM + kb * 64 + c * 8;
        const size_t gb = (size_t)(bn + r) * DM + kb * 64 + c * 8;
        cp16(st + sw,            Ah + ga);
        cp16(st + TILE_B + sw,   Al + ga);
        cp16(st + 2*TILE_B + sw, Bh + gb);
        cp16(st + 3*TILE_B + sw, Bl + gb);
    }
}

template<int MODE>
__global__ __launch_bounds__(512, 1) void gemm_tc(
    const float* __restrict__ b1,
    const float* __restrict__ b2,
    const float* __restrict__ b3,
    float* __restrict__ outp)
{
    extern __shared__ char smraw[];
    char* tiles = (char*)(((uintptr_t)smraw + 1023) & ~(uintptr_t)1023);
    const uint32_t tiles32 = smem_u32(tiles);

    const int tid  = threadIdx.x;
    const int wid  = tid >> 5;
    const int lane = tid & 31;
    const int bm = blockIdx.y * 128;
    const int bn = blockIdx.x * 128;

    const __nv_bfloat16 *Ah, *Al, *Bh, *Bl;
    const float* bias;
    if (MODE == 0) {
        const int z = blockIdx.z;
        Ah = g_xhi; Al = g_xlo;
        Bh = g_whi + (size_t)z * DM * DM;
        Bl = g_wlo + (size_t)z * DM * DM;
        bias = (z == 0) ? b1 : (z == 1) ? b2 : b3;
    } else {
        Ah = g_chi; Al = g_clo; Bh = g_wohi; Bl = g_wolo;
        bias = b1;
    }

    // ldmatrix lane addressing
    const int lrow = (lane & 7) | (((lane >> 3) & 1) << 3);  // 0..15
    const int lkh  = lane >> 4;                              // k half 0/1
    const int r7   = lane & 7;
    const int wm   = (wid >> 2) * 32;
    const int wn   = (wid & 3) * 32;

    float acc[2][4][4];
    #pragma unroll
    for (int i = 0; i < 2; i++)
        #pragma unroll
        for (int j = 0; j < 4; j++)
            #pragma unroll
            for (int c = 0; c < 4; c++) acc[i][j][c] = 0.f;

    // prologue: stages 0,1 in flight
    issue_stage(Ah, Al, Bh, Bl, tiles32 + 0*STAGE_B, tid, 0, bm, bn);
    CP_COMMIT();
    issue_stage(Ah, Al, Bh, Bl, tiles32 + 1*STAGE_B, tid, 1, bm, bn);
    CP_COMMIT();

    int slot = 0;
    for (int kb = 0; kb < 16; kb++) {
        if (kb < 15) asm volatile("cp.async.wait_group 1;" ::: "memory");
        else         asm volatile("cp.async.wait_group 0;" ::: "memory");
        __syncthreads();

        if (kb + 2 < 16) {
            int ns = slot + 2; if (ns >= STAGES) ns -= STAGES;
            issue_stage(Ah, Al, Bh, Bl, tiles32 + ns*STAGE_B, tid, kb + 2, bm, bn);
            CP_COMMIT();
        }

        const uint32_t Ahi = tiles32 + slot * STAGE_B;
        const uint32_t Alo = Ahi + TILE_B;
        const uint32_t Bhi = Ahi + 2*TILE_B;
        const uint32_t Blo = Ahi + 3*TILE_B;

        #pragma unroll
        for (int k16 = 0; k16 < 4; k16++) {
            uint32_t ahi[2][4], alo[2][4], bhi[2][4], blo[2][4];
            const int ck = ((2*k16 + lkh) ^ r7) * 16;
            #pragma unroll
            for (int i = 0; i < 2; i++) {
                const uint32_t ro = (uint32_t)(wm + i*16 + lrow) * 128 + ck;
                LDSM4(ahi[i][0], ahi[i][1], ahi[i][2], ahi[i][3], Ahi + ro);
                LDSM4(alo[i][0], alo[i][1], alo[i][2], alo[i][3], Alo + ro);
            }
            #pragma unroll
            for (int p = 0; p < 2; p++) {
                const uint32_t ro = (uint32_t)(wn + p*16 + lrow) * 128 + ck;
                LDSM4(bhi[p][0], bhi[p][1], bhi[p][2], bhi[p][3], Bhi + ro);
                LDSM4(blo[p][0], blo[p][1], blo[p][2], blo[p][3], Blo + ro);
            }
            #pragma unroll
            for (int i = 0; i < 2; i++)
                #pragma unroll
                for (int jn = 0; jn < 4; jn++) {
                    const int p = jn >> 1, q = jn & 1;
                    MMA16816(acc[i][jn], ahi[i][0], ahi[i][1], ahi[i][2], ahi[i][3],
                             bhi[p][q], bhi[p][q+2]);
                    MMA16816(acc[i][jn], ahi[i][0], ahi[i][1], ahi[i][2], ahi[i][3],
                             blo[p][q], blo[p][q+2]);
                    MMA16816(acc[i][jn], alo[i][0], alo[i][1], alo[i][2], alo[i][3],
                             bhi[p][q], bhi[p][q+2]);
                }
        }
        slot++; if (slot >= STAGES) slot = 0;
    }

    // ---- epilogue: D-fragment scatter + bias ----
    const int qrow = lane >> 2;
    const int qcol = (lane & 3) * 2;
    #pragma unroll
    for (int jn = 0; jn < 4; jn++) {
        const int col = bn + wn + jn*8 + qcol;
        const float bx = bias[col], by = bias[col + 1];
        #pragma unroll
        for (int i = 0; i < 2; i++) {
            const int row0 = bm + wm + i*16 + qrow;
            #pragma unroll
            for (int hh = 0; hh < 2; hh++) {
                const int row = row0 + hh*8;
                float ox = acc[i][jn][2*hh+0] + bx;
                float oy = acc[i][jn][2*hh+1] + by;
                if (MODE == 0) {
                    const int z = blockIdx.z;
                    float* out = (z == 0) ? g_q : (z == 1) ? g_k : g_v;
                    const int b = row >> 11;
                    const int s = row & 2047;
                    const int h = col >> 6;
                    const int d = col & 63;
                    float2 o;
                    o.x = __uint_as_float(cvt_tf32(ox));
                    o.y = __uint_as_float(cvt_tf32(oy));
                    *(float2*)(out + ((((size_t)b * NH + h) * SS + s) * DH + d)) = o;
                } else {
                    float2 o = make_float2(ox, oy);
                    *(float2*)(outp + (size_t)row * DM + col) = o;
                }
            }
        }
    }
}

// ============================================================
// Flash attention: tf32 mma.sync, causal, online softmax in exp2 domain.
// Epilogue now writes ctx as bf16 hi/lo (feeds out-projection directly).
// ============================================================
#define KSTR 68
#define VSTR 68
#define PSTR 72
#define ATT_SMEM_BYTES ((64*KSTR + 64*VSTR + 64*PSTR) * 4)

__global__ __launch_bounds__(128) void attn_tc()
{
    extern __shared__ float smf[];
    float* Ks = smf;
    float* Vs = smf + 64*KSTR;
    float* Ps = smf + 64*(KSTR+VSTR);

    const int tid  = threadIdx.x;
    const int lane = tid & 31;
    const int wid  = tid >> 5;
    const int it   = (int)gridDim.x - 1 - (int)blockIdx.x;
    const int bh   = blockIdx.y;

    const float* Qb = g_q + (size_t)bh * SS * DH;
    const float* Kb = g_k + (size_t)bh * SS * DH;
    const float* Vb = g_v + (size_t)bh * SS * DH;

    const int qr = lane >> 2;
    const int qc = lane & 3;
    const int row_lo = wid * 16 + qr;
    const int row_hi = row_lo + 8;

    uint32_t qf[8][4];
    #pragma unroll
    for (int kk = 0; kk < 8; kk++) {
        const int k0 = kk*8 + qc;
        qf[kk][0] = __float_as_uint(Qb[(size_t)(it*64 + row_lo)*DH + k0]);
        qf[kk][1] = __float_as_uint(Qb[(size_t)(it*64 + row_hi)*DH + k0]);
        qf[kk][2] = __float_as_uint(Qb[(size_t)(it*64 + row_lo)*DH + k0 + 4]);
        qf[kk][3] = __float_as_uint(Qb[(size_t)(it*64 + row_hi)*DH + k0 + 4]);
    }

    const float SC = 0.18033688f;        // (1/8) * log2(e)
    float m0 = -1e30f, m1 = -1e30f, l0 = 0.f, l1 = 0.f;
    float o[8][4];
    #pragma unroll
    for (int nt = 0; nt < 8; nt++)
        #pragma unroll
        for (int c = 0; c < 4; c++) o[nt][c] = 0.f;

    const int lrow = tid >> 1;
    const int lcol = (tid & 1) * 32;

    for (int jt = 0; jt <= it; jt++) {
        {
            const float4* kp = (const float4*)(Kb + (size_t)(jt*64 + lrow)*DH + lcol);
            const float4* vp = (const float4*)(Vb + (size_t)(jt*64 + lrow)*DH + lcol);
            #pragma unroll
            for (int v = 0; v < 8; v++) {
                *(float4*)&Ks[lrow*KSTR + lcol + v*4] = kp[v];
                *(float4*)&Vs[lrow*VSTR + lcol + v*4] = vp[v];
            }
        }
        __syncthreads();

        float s[8][4];
        #pragma unroll
        for (int nt = 0; nt < 8; nt++)
            #pragma unroll
            for (int c = 0; c < 4; c++) s[nt][c] = 0.f;

        #pragma unroll
        for (int kk = 0; kk < 8; kk++) {
            #pragma unroll
            for (int nt = 0; nt < 8; nt++) {
                const uint32_t b0 = __float_as_uint(Ks[(nt*8 + qr)*KSTR + kk*8 + qc]);
                const uint32_t b1 = __float_as_uint(Ks[(nt*8 + qr)*KSTR + kk*8 + qc + 4]);
                MMA_TF32(s[nt], qf[kk][0], qf[kk][1], qf[kk][2], qf[kk][3], b0, b1);
            }
        }

        if (jt == it) {
            #pragma unroll
            for (int nt = 0; nt < 8; nt++) {
                const int c0 = nt*8 + qc*2;
                if (c0     > row_lo) s[nt][0] = -1e30f;
                if (c0 + 1 > row_lo) s[nt][1] = -1e30f;
                if (c0     > row_hi) s[nt][2] = -1e30f;
                if (c0 + 1 > row_hi) s[nt][3] = -1e30f;
            }
        }

        float tm0 = -1e30f, tm1 = -1e30f;
        #pragma unroll
        for (int nt = 0; nt < 8; nt++) {
            tm0 = fmaxf(tm0, fmaxf(s[nt][0], s[nt][1]));
            tm1 = fmaxf(tm1, fmaxf(s[nt][2], s[nt][3]));
        }
        tm0 = fmaxf(tm0, __shfl_xor_sync(0xffffffffu, tm0, 1));
        tm0 = fmaxf(tm0, __shfl_xor_sync(0xffffffffu, tm0, 2));
        tm1 = fmaxf(tm1, __shfl_xor_sync(0xffffffffu, tm1, 1));
        tm1 = fmaxf(tm1, __shfl_xor_sync(0xffffffffu, tm1, 2));

        const float mn0 = fmaxf(m0, tm0);
        const float mn1 = fmaxf(m1, tm1);
        const float corr0 = ex2_fast((m0 - mn0) * SC);
        const float corr1 = ex2_fast((m1 - mn1) * SC);
        m0 = mn0; m1 = mn1;
        const float nms0 = -mn0 * SC;
        const float nms1 = -mn1 * SC;

        float ls0 = 0.f, ls1 = 0.f;
        #pragma unroll
        for (int nt = 0; nt < 8; nt++) {
            const float p0 = ex2_fast(fmaf(s[nt][0], SC, nms0));
            const float p1 = ex2_fast(fmaf(s[nt][1], SC, nms0));
            const float p2 = ex2_fast(fmaf(s[nt][2], SC, nms1));
            const float p3 = ex2_fast(fmaf(s[nt][3], SC, nms1));
            ls0 += p0 + p1;
            ls1 += p2 + p3;
            uint2 plo = make_uint2(cvt_tf32(p0), cvt_tf32(p1));
            uint2 phi = make_uint2(cvt_tf32(p2), cvt_tf32(p3));
            *(uint2*)&Ps[row_lo*PSTR + nt*8 + qc*2] = plo;
            *(uint2*)&Ps[row_hi*PSTR + nt*8 + qc*2] = phi;
        }
        ls0 += __shfl_xor_sync(0xffffffffu, ls0, 1);
        ls0 += __shfl_xor_sync(0xffffffffu, ls0, 2);
        ls1 += __shfl_xor_sync(0xffffffffu, ls1, 1);
        ls1 += __shfl_xor_sync(0xffffffffu, ls1, 2);
        l0 = l0 * corr0 + ls0;
        l1 = l1 * corr1 + ls1;

        #pragma unroll
        for (int nt = 0; nt < 8; nt++) {
            o[nt][0] *= corr0; o[nt][1] *= corr0;
            o[nt][2] *= corr1; o[nt][3] *= corr1;
        }
        __syncwarp();

        #pragma unroll
        for (int kt = 0; kt < 8; kt++) {
            const uint32_t a0 = __float_as_uint(Ps[row_lo*PSTR + kt*8 + qc]);
            const uint32_t a1 = __float_as_uint(Ps[row_hi*PSTR + kt*8 + qc]);
            const uint32_t a2 = __float_as_uint(Ps[row_lo*PSTR + kt*8 + qc + 4]);
            const uint32_t a3 = __float_as_uint(Ps[row_hi*PSTR + kt*8 + qc + 4]);
            #pragma unroll
            for (int nt = 0; nt < 8; nt++) {
                const uint32_t b0 = __float_as_uint(Vs[(kt*8 + qc)*VSTR + nt*8 + qr]);
                const uint32_t b1 = __float_as_uint(Vs[(kt*8 + qc + 4)*VSTR + nt*8 + qr]);
                MMA_TF32(o[nt], a0, a1, a2, a3, b0, b1);
            }
        }
        __syncthreads();
    }

    // ---- epilogue: normalize, split to bf16 hi/lo ctx ----
    const int b = bh >> 4;
    const int h = bh & 15;
    const float i0 = 1.f / l0;
    const float i1 = 1.f / l1;
    const size_t r0off = (size_t)(b*SS + it*64 + row_lo) * DM;
    const size_t r1off = (size_t)(b*SS + it*64 + row_hi) * DM;
    #pragma unroll
    for (int nt = 0; nt < 8; nt++) {
        const int d = h*64 + nt*8 + qc*2;
        float w0x = o[nt][0] * i0, w0y = o[nt][1] * i0;
        float w1x = o[nt][2] * i1, w1y = o[nt][3] * i1;
        __nv_bfloat162 h0 = __floats2bfloat162_rn(w0x, w0y);
        __nv_bfloat162 h1 = __floats2bfloat162_rn(w1x, w1y);
        __nv_bfloat162 l0v = __floats2bfloat162_rn(w0x - __bfloat162float(h0.x),
                                                   w0y - __bfloat162float(h0.y));
        __nv_bfloat162 l1v = __floats2bfloat162_rn(w1x - __bfloat162float(h1.x),
                                                   w1y - __bfloat162float(h1.y));
        *(__nv_bfloat162*)&g_chi[r0off + d] = h0;
        *(__nv_bfloat162*)&g_clo[r0off + d] = l0v;
        *(__nv_bfloat162*)&g_chi[r1off + d] = h1;
        *(__nv_bfloat162*)&g_clo[r1off + d] = l1v;
    }
}

// ============================================================
extern "C" void kernel_launch(void* const* d_in, const int* in_sizes, int n_in,
                              void* d_out, int out_size)
{
    const float* x  = (const float*)d_in[0];
    const float* Wq = (const float*)d_in[1];
    const float* bq = (const float*)d_in[2];
    const float* Wk = (const float*)d_in[3];
    const float* bk = (const float*)d_in[4];
    const float* Wv = (const float*)d_in[5];
    const float* bv = (const float*)d_in[6];
    const float* Wo = (const float*)d_in[7];
    const float* bo = (const float*)d_in[8];
    float* out = (float*)d_out;

    cudaFuncSetAttribute(gemm_tc<0>, cudaFuncAttributeMaxDynamicSharedMemorySize, GEMM_SMEM_BYTES);
    cudaFuncSetAttribute(gemm_tc<1>, cudaFuncAttributeMaxDynamicSharedMemorySize, GEMM_SMEM_BYTES);
    cudaFuncSetAttribute(attn_tc, cudaFuncAttributeMaxDynamicSharedMemorySize, ATT_SMEM_BYTES);

    prep_split<<<dim3(MM*DM/4/256, 5), 256>>>(x, Wq, Wk, Wv, Wo);
    gemm_tc<0><<<dim3(DM / 128, MM / 128, 3), 512, GEMM_SMEM_BYTES>>>(bq, bk, bv, nullptr);
    attn_tc<<<dim3(SS / 64, BB * NH), 128, ATT_SMEM_BYTES>>>();
    gemm_tc<1><<<dim3(DM / 128, MM / 128), 512, GEMM_SMEM_BYTES>>>(bo, nullptr, nullptr, out);
}

// round 13
// speedup vs baseline: 3.2600x; 1.4289x over previous
#include <cuda_runtime.h>
#include <cuda_bf16.h>
#include <cstdint>
#include <math.h>

// Problem constants
#define BB   2
#define SS   2048
#define DM   1024
#define NH   16
#define DH   64
#define MM   (BB*SS)

// -------- scratch (device globals; allocation-free) --------
__device__ float g_q[BB*NH*SS*DH];                       // [b][h][s][d] tf32 bits
__device__ float g_k[BB*NH*SS*DH];
__device__ float g_v[BB*NH*SS*DH];
__device__ __align__(16) __nv_bfloat16 g_xhi[MM*DM];     // X split
__device__ __align__(16) __nv_bfloat16 g_xlo[MM*DM];
__device__ __align__(16) __nv_bfloat16 g_whi[3*DM*DM];   // Wq,Wk,Wv split
__device__ __align__(16) __nv_bfloat16 g_wlo[3*DM*DM];
__device__ __align__(16) __nv_bfloat16 g_wohi[DM*DM];    // Wo split
__device__ __align__(16) __nv_bfloat16 g_wolo[DM*DM];
__device__ __align__(16) __nv_bfloat16 g_chi[MM*DM];     // ctx split (attention out)
__device__ __align__(16) __nv_bfloat16 g_clo[MM*DM];

// ============================================================
// helpers
// ============================================================
__device__ __forceinline__ uint32_t smem_u32(const void* p) {
    uint32_t a;
    asm("{ .reg .u64 t; cvta.to.shared.u64 t, %1; cvt.u32.u64 %0, t; }" : "=r"(a) : "l"(p));
    return a;
}
__device__ __forceinline__ uint32_t cvt_tf32(float a) {
    uint32_t r;
    asm("cvt.rna.tf32.f32 %0, %1;" : "=r"(r) : "f"(a));
    return r;
}
__device__ __forceinline__ float ex2_fast(float x) {
    float r;
    asm("ex2.approx.ftz.f32 %0, %1;" : "=f"(r) : "f"(x));
    return r;
}
__device__ __forceinline__ void cp16(uint32_t dst_smem, const void* src) {
    uint64_t g;
    asm("cvta.to.global.u64 %0, %1;" : "=l"(g) : "l"(src));
    asm volatile("cp.async.cg.shared.global [%0], [%1], 16;" :: "r"(dst_smem), "l"(g));
}
#define CP_COMMIT() asm volatile("cp.async.commit_group;" ::: "memory")

#define LDSM4(d0, d1, d2, d3, addr)                                            \
    asm volatile("ldmatrix.sync.aligned.m8n8.x4.shared.b16 {%0,%1,%2,%3}, [%4];" \
                 : "=r"(d0), "=r"(d1), "=r"(d2), "=r"(d3) : "r"(addr))

#define MMA16816(c, a0, a1, a2, a3, b0, b1)                                    \
    asm volatile("mma.sync.aligned.m16n8k16.row.col.f32.bf16.bf16.f32 "        \
                 "{%0,%1,%2,%3}, {%4,%5,%6,%7}, {%8,%9}, {%0,%1,%2,%3};"       \
                 : "+f"((c)[0]), "+f"((c)[1]), "+f"((c)[2]), "+f"((c)[3])      \
                 : "r"(a0), "r"(a1), "r"(a2), "r"(a3), "r"(b0), "r"(b1))

#define MMA_TF32(c, a0, a1, a2, a3, b0, b1)                                    \
    asm volatile("mma.sync.aligned.m16n8k8.row.col.f32.tf32.tf32.f32 "         \
                 "{%0,%1,%2,%3}, {%4,%5,%6,%7}, {%8,%9}, {%0,%1,%2,%3};"       \
                 : "+f"((c)[0]), "+f"((c)[1]), "+f"((c)[2]), "+f"((c)[3])      \
                 : "r"(a0), "r"(a1), "r"(a2), "r"(a3), "r"(b0), "r"(b1))

// ============================================================
// Pre-pass: split fp32 tensors into bf16 hi/lo (once per launch).
// ============================================================
__global__ __launch_bounds__(256) void prep_split(
    const float* __restrict__ x,
    const float* __restrict__ wq, const float* __restrict__ wk,
    const float* __restrict__ wv, const float* __restrict__ wo)
{
    const int z = blockIdx.y;
    const float* src;
    __nv_bfloat16* hi;
    __nv_bfloat16* lo;
    int n4;
    if (z == 0)      { src = x;  hi = g_xhi;             lo = g_xlo;             n4 = MM*DM/4; }
    else if (z == 1) { src = wq; hi = g_whi;             lo = g_wlo;             n4 = DM*DM/4; }
    else if (z == 2) { src = wk; hi = g_whi + DM*DM;     lo = g_wlo + DM*DM;     n4 = DM*DM/4; }
    else if (z == 3) { src = wv; hi = g_whi + 2*DM*DM;   lo = g_wlo + 2*DM*DM;   n4 = DM*DM/4; }
    else             { src = wo; hi = g_wohi;            lo = g_wolo;            n4 = DM*DM/4; }

    const int idx = blockIdx.x * 256 + threadIdx.x;
    if (idx >= n4) return;
    float4 v = ((const float4*)src)[idx];
    __nv_bfloat162 h01 = __floats2bfloat162_rn(v.x, v.y);
    __nv_bfloat162 h23 = __floats2bfloat162_rn(v.z, v.w);
    __nv_bfloat162 l01 = __floats2bfloat162_rn(v.x - __bfloat162float(h01.x),
                                               v.y - __bfloat162float(h01.y));
    __nv_bfloat162 l23 = __floats2bfloat162_rn(v.z - __bfloat162float(h23.x),
                                               v.w - __bfloat162float(h23.y));
    ((__nv_bfloat162*)hi)[2*idx]   = h01;
    ((__nv_bfloat162*)hi)[2*idx+1] = h23;
    ((__nv_bfloat162*)lo)[2*idx]   = l01;
    ((__nv_bfloat162*)lo)[2*idx+1] = l23;
}

// ============================================================
// bf16-split tensor-core GEMM, pre-converted inputs, cp.async 3-stage.
// (unchanged from R12)
// ============================================================
#define TILE_B   16384
#define STAGE_B  (4*TILE_B)
#define STAGES   3
#define GEMM_SMEM_BYTES (1024 + STAGES*STAGE_B)

__device__ __forceinline__ void issue_stage(
    const __nv_bfloat16* __restrict__ Ah, const __nv_bfloat16* __restrict__ Al,
    const __nv_bfloat16* __restrict__ Bh, const __nv_bfloat16* __restrict__ Bl,
    uint32_t st, int tid, int kb, int bm, int bn)
{
    #pragma unroll
    for (int t = 0; t < 2; t++) {
        const int id = tid + t * 512;
        const int r  = id >> 3;
        const int c  = id & 7;
        const uint32_t sw = (uint32_t)(r * 128 + ((c ^ (r & 7)) << 4));
        const size_t ga = (size_t)(bm + r) * DM + kb * 64 + c * 8;
        const size_t gb = (size_t)(bn + r) * DM + kb * 64 + c * 8;
        cp16(st + sw,            Ah + ga);
        cp16(st + TILE_B + sw,   Al + ga);
        cp16(st + 2*TILE_B + sw, Bh + gb);
        cp16(st + 3*TILE_B + sw, Bl + gb);
    }
}

template<int MODE>
__global__ __launch_bounds__(512, 1) void gemm_tc(
    const float* __restrict__ b1,
    const float* __restrict__ b2,
    const float* __restrict__ b3,
    float* __restrict__ outp)
{
    extern __shared__ char smraw[];
    char* tiles = (char*)(((uintptr_t)smraw + 1023) & ~(uintptr_t)1023);
    const uint32_t tiles32 = smem_u32(tiles);

    const int tid  = threadIdx.x;
    const int wid  = tid >> 5;
    const int lane = tid & 31;
    const int bm = blockIdx.y * 128;
    const int bn = blockIdx.x * 128;

    const __nv_bfloat16 *Ah, *Al, *Bh, *Bl;
    const float* bias;
    if (MODE == 0) {
        const int z = blockIdx.z;
        Ah = g_xhi; Al = g_xlo;
        Bh = g_whi + (size_t)z * DM * DM;
        Bl = g_wlo + (size_t)z * DM * DM;
        bias = (z == 0) ? b1 : (z == 1) ? b2 : b3;
    } else {
        Ah = g_chi; Al = g_clo; Bh = g_wohi; Bl = g_wolo;
        bias = b1;
    }

    const int lrow = (lane & 7) | (((lane >> 3) & 1) << 3);
    const int lkh  = lane >> 4;
    const int r7   = lane & 7;
    const int wm   = (wid >> 2) * 32;
    const int wn   = (wid & 3) * 32;

    float acc[2][4][4];
    #pragma unroll
    for (int i = 0; i < 2; i++)
        #pragma unroll
        for (int j = 0; j < 4; j++)
            #pragma unroll
            for (int c = 0; c < 4; c++) acc[i][j][c] = 0.f;

    issue_stage(Ah, Al, Bh, Bl, tiles32 + 0*STAGE_B, tid, 0, bm, bn);
    CP_COMMIT();
    issue_stage(Ah, Al, Bh, Bl, tiles32 + 1*STAGE_B, tid, 1, bm, bn);
    CP_COMMIT();

    int slot = 0;
    for (int kb = 0; kb < 16; kb++) {
        if (kb < 15) asm volatile("cp.async.wait_group 1;" ::: "memory");
        else         asm volatile("cp.async.wait_group 0;" ::: "memory");
        __syncthreads();

        if (kb + 2 < 16) {
            int ns = slot + 2; if (ns >= STAGES) ns -= STAGES;
            issue_stage(Ah, Al, Bh, Bl, tiles32 + ns*STAGE_B, tid, kb + 2, bm, bn);
            CP_COMMIT();
        }

        const uint32_t Ahi = tiles32 + slot * STAGE_B;
        const uint32_t Alo = Ahi + TILE_B;
        const uint32_t Bhi = Ahi + 2*TILE_B;
        const uint32_t Blo = Ahi + 3*TILE_B;

        #pragma unroll
        for (int k16 = 0; k16 < 4; k16++) {
            uint32_t ahi[2][4], alo[2][4], bhi[2][4], blo[2][4];
            const int ck = ((2*k16 + lkh) ^ r7) * 16;
            #pragma unroll
            for (int i = 0; i < 2; i++) {
                const uint32_t ro = (uint32_t)(wm + i*16 + lrow) * 128 + ck;
                LDSM4(ahi[i][0], ahi[i][1], ahi[i][2], ahi[i][3], Ahi + ro);
                LDSM4(alo[i][0], alo[i][1], alo[i][2], alo[i][3], Alo + ro);
            }
            #pragma unroll
            for (int p = 0; p < 2; p++) {
                const uint32_t ro = (uint32_t)(wn + p*16 + lrow) * 128 + ck;
                LDSM4(bhi[p][0], bhi[p][1], bhi[p][2], bhi[p][3], Bhi + ro);
                LDSM4(blo[p][0], blo[p][1], blo[p][2], blo[p][3], Blo + ro);
            }
            #pragma unroll
            for (int i = 0; i < 2; i++)
                #pragma unroll
                for (int jn = 0; jn < 4; jn++) {
                    const int p = jn >> 1, q = jn & 1;
                    MMA16816(acc[i][jn], ahi[i][0], ahi[i][1], ahi[i][2], ahi[i][3],
                             bhi[p][q], bhi[p][q+2]);
                    MMA16816(acc[i][jn], ahi[i][0], ahi[i][1], ahi[i][2], ahi[i][3],
                             blo[p][q], blo[p][q+2]);
                    MMA16816(acc[i][jn], alo[i][0], alo[i][1], alo[i][2], alo[i][3],
                             bhi[p][q], bhi[p][q+2]);
                }
        }
        slot++; if (slot >= STAGES) slot = 0;
    }

    const int qrow = lane >> 2;
    const int qcol = (lane & 3) * 2;
    #pragma unroll
    for (int jn = 0; jn < 4; jn++) {
        const int col = bn + wn + jn*8 + qcol;
        const float bx = bias[col], by = bias[col + 1];
        #pragma unroll
        for (int i = 0; i < 2; i++) {
            const int row0 = bm + wm + i*16 + qrow;
            #pragma unroll
            for (int hh = 0; hh < 2; hh++) {
                const int row = row0 + hh*8;
                float ox = acc[i][jn][2*hh+0] + bx;
                float oy = acc[i][jn][2*hh+1] + by;
                if (MODE == 0) {
                    const int z = blockIdx.z;
                    float* out = (z == 0) ? g_q : (z == 1) ? g_k : g_v;
                    const int b = row >> 11;
                    const int s = row & 2047;
                    const int h = col >> 6;
                    const int d = col & 63;
                    float2 o;
                    o.x = __uint_as_float(cvt_tf32(ox));
                    o.y = __uint_as_float(cvt_tf32(oy));
                    *(float2*)(out + ((((size_t)b * NH + h) * SS + s) * DH + d)) = o;
                } else {
                    float2 o = make_float2(ox, oy);
                    *(float2*)(outp + (size_t)row * DM + col) = o;
                }
            }
        }
    }
}

// ============================================================
// Flash attention v3: tf32 mma.sync, causal, exp2-domain online softmax.
// 256 threads (8 warps), 128 q-rows/CTA, 64 keys/iter.
// cp.async double-buffered K/V; one __syncthreads per iteration.
// k-permuted fragments: QK B-operand and PV A-operand are float2 LDS.64.
// Strides: KSTR=72, PSTR=72, VSTR=68 (conflict-free for these patterns).
// ============================================================
#define KSTR 72
#define VSTR 68
#define PSTR 72
#define ATT_SMEM_BYTES ((2*64*KSTR + 2*64*VSTR + 128*PSTR) * 4)

__global__ __launch_bounds__(256, 2) void attn_tc()
{
    extern __shared__ float smf[];
    float* Kbuf = smf;                              // [2][64*KSTR]
    float* Vbuf = smf + 2*64*KSTR;                  // [2][64*VSTR]
    float* Ps   = smf + 2*64*KSTR + 2*64*VSTR;      // [128*PSTR]
    const uint32_t KbufA = smem_u32(Kbuf);
    const uint32_t VbufA = smem_u32(Vbuf);

    const int tid  = threadIdx.x;
    const int lane = tid & 31;
    const int wid  = tid >> 5;                       // 0..7
    const int it   = (int)gridDim.x - 1 - (int)blockIdx.x;  // heavy tiles first
    const int bh   = blockIdx.y;

    const float* Qb = g_q + (size_t)bh * SS * DH;
    const float* Kb = g_k + (size_t)bh * SS * DH;
    const float* Vb = g_v + (size_t)bh * SS * DH;

    const int qr = lane >> 2;            // 0..7
    const int qc = lane & 3;             // 0..3
    const int row_lo = wid * 16 + qr;    // local q row (0..127)
    const int row_hi = row_lo + 8;
    const int qg_lo = it * 128 + row_lo; // global q row
    const int qg_hi = it * 128 + row_hi;

    // Q fragments, k-permuted: logical k=qc -> phys 2qc, k=qc+4 -> 2qc+1
    uint32_t qf[8][4];
    #pragma unroll
    for (int kk = 0; kk < 8; kk++) {
        const float2 qlo = *(const float2*)&Qb[(size_t)qg_lo * DH + kk*8 + 2*qc];
        const float2 qhi = *(const float2*)&Qb[(size_t)qg_hi * DH + kk*8 + 2*qc];
        qf[kk][0] = __float_as_uint(qlo.x);
        qf[kk][1] = __float_as_uint(qhi.x);
        qf[kk][2] = __float_as_uint(qlo.y);
        qf[kk][3] = __float_as_uint(qhi.y);
    }

    const float SC = 0.18033688f;        // (1/8) * log2(e)
    float m0 = -1e30f, m1 = -1e30f, l0 = 0.f, l1 = 0.f;
    float o[8][4];
    #pragma unroll
    for (int nt = 0; nt < 8; nt++)
        #pragma unroll
        for (int c = 0; c < 4; c++) o[nt][c] = 0.f;

    // ---- cp.async tile fill: K+V, 4 cp16 each per thread ----
    // prologue: tile 0 into buffer 0
    {
        #pragma unroll
        for (int t2 = 0; t2 < 4; t2++) {
            const int id  = tid + t2 * 256;
            const int row = id >> 4;
            const int c   = (id & 15) * 4;
            cp16(KbufA + (uint32_t)(row*KSTR + c) * 4, Kb + (size_t)row * DH + c);
            cp16(VbufA + (uint32_t)(row*VSTR + c) * 4, Vb + (size_t)row * DH + c);
        }
        CP_COMMIT();
    }

    const int jtmax = 2 * it + 1;
    for (int jt = 0; jt <= jtmax; jt++) {
        asm volatile("cp.async.wait_group 0;" ::: "memory");
        __syncthreads();   // tile jt visible to all; all reads of buf^1 (iter jt-1) done

        if (jt < jtmax) {
            const uint32_t kb = KbufA + (uint32_t)(((jt+1) & 1) * 64 * KSTR) * 4;
            const uint32_t vb = VbufA + (uint32_t)(((jt+1) & 1) * 64 * VSTR) * 4;
            const float* Kg = Kb + (size_t)(jt+1) * 64 * DH;
            const float* Vg = Vb + (size_t)(jt+1) * 64 * DH;
            #pragma unroll
            for (int t2 = 0; t2 < 4; t2++) {
                const int id  = tid + t2 * 256;
                const int row = id >> 4;
                const int c   = (id & 15) * 4;
                cp16(kb + (uint32_t)(row*KSTR + c) * 4, Kg + (size_t)row * DH + c);
                cp16(vb + (uint32_t)(row*VSTR + c) * 4, Vg + (size_t)row * DH + c);
            }
            CP_COMMIT();
        }

        const float* Ks = Kbuf + (jt & 1) * 64 * KSTR;
        const float* Vs = Vbuf + (jt & 1) * 64 * VSTR;

        // ---- S = Q K^T ----
        float s[8][4];
        #pragma unroll
        for (int nt = 0; nt < 8; nt++)
            #pragma unroll
            for (int c = 0; c < 4; c++) s[nt][c] = 0.f;

        #pragma unroll
        for (int kk = 0; kk < 8; kk++) {
            #pragma unroll
            for (int nt = 0; nt < 8; nt++) {
                const float2 b2v = *(const float2*)&Ks[(nt*8 + qr)*KSTR + kk*8 + 2*qc];
                MMA_TF32(s[nt], qf[kk][0], qf[kk][1], qf[kk][2], qf[kk][3],
                         __float_as_uint(b2v.x), __float_as_uint(b2v.y));
            }
        }

        // ---- causal mask (last two key tiles only) ----
        if (jt >= 2*it) {
            #pragma unroll
            for (int nt = 0; nt < 8; nt++) {
                const int t0 = jt*64 + nt*8 + qc*2;
                if (t0     > qg_lo) s[nt][0] = -1e30f;
                if (t0 + 1 > qg_lo) s[nt][1] = -1e30f;
                if (t0     > qg_hi) s[nt][2] = -1e30f;
                if (t0 + 1 > qg_hi) s[nt][3] = -1e30f;
            }
        }

        // ---- online softmax (exp2 domain) ----
        float tm0 = -1e30f, tm1 = -1e30f;
        #pragma unroll
        for (int nt = 0; nt < 8; nt++) {
            tm0 = fmaxf(tm0, fmaxf(s[nt][0], s[nt][1]));
            tm1 = fmaxf(tm1, fmaxf(s[nt][2], s[nt][3]));
        }
        tm0 = fmaxf(tm0, __shfl_xor_sync(0xffffffffu, tm0, 1));
        tm0 = fmaxf(tm0, __shfl_xor_sync(0xffffffffu, tm0, 2));
        tm1 = fmaxf(tm1, __shfl_xor_sync(0xffffffffu, tm1, 1));
        tm1 = fmaxf(tm1, __shfl_xor_sync(0xffffffffu, tm1, 2));

        const float mn0 = fmaxf(m0, tm0);
        const float mn1 = fmaxf(m1, tm1);
        const float corr0 = ex2_fast((m0 - mn0) * SC);
        const float corr1 = ex2_fast((m1 - mn1) * SC);
        m0 = mn0; m1 = mn1;
        const float nms0 = -mn0 * SC;
        const float nms1 = -mn1 * SC;

        float ls0 = 0.f, ls1 = 0.f;
        #pragma unroll
        for (int nt = 0; nt < 8; nt++) {
            const float p0 = ex2_fast(fmaf(s[nt][0], SC, nms0));
            const float p1 = ex2_fast(fmaf(s[nt][1], SC, nms0));
            const float p2 = ex2_fast(fmaf(s[nt][2], SC, nms1));
            const float p3 = ex2_fast(fmaf(s[nt][3], SC, nms1));
            ls0 += p0 + p1;
            ls1 += p2 + p3;
            uint2 plo = make_uint2(cvt_tf32(p0), cvt_tf32(p1));
            uint2 phi = make_uint2(cvt_tf32(p2), cvt_tf32(p3));
            *(uint2*)&Ps[row_lo*PSTR + nt*8 + qc*2] = plo;
            *(uint2*)&Ps[row_hi*PSTR + nt*8 + qc*2] = phi;
        }
        ls0 += __shfl_xor_sync(0xffffffffu, ls0, 1);
        ls0 += __shfl_xor_sync(0xffffffffu, ls0, 2);
        ls1 += __shfl_xor_sync(0xffffffffu, ls1, 1);
        ls1 += __shfl_xor_sync(0xffffffffu, ls1, 2);
        l0 = l0 * corr0 + ls0;
        l1 = l1 * corr1 + ls1;

        #pragma unroll
        for (int nt = 0; nt < 8; nt++) {
            o[nt][0] *= corr0; o[nt][1] *= corr0;
            o[nt][2] *= corr1; o[nt][3] *= corr1;
        }
        __syncwarp();   // P rows are warp-private (produced & consumed in-warp)

        // ---- O += P V (k-permuted: A float2 pairs; B scalar rows t, t+1) ----
        #pragma unroll
        for (int kt = 0; kt < 8; kt++) {
            const float2 alo = *(const float2*)&Ps[row_lo*PSTR + kt*8 + 2*qc];
            const float2 ahi = *(const float2*)&Ps[row_hi*PSTR + kt*8 + 2*qc];
            const uint32_t a0 = __float_as_uint(alo.x);
            const uint32_t a1 = __float_as_uint(ahi.x);
            const uint32_t a2 = __float_as_uint(alo.y);
            const uint32_t a3 = __float_as_uint(ahi.y);
            const int tr0 = (kt*8 + 2*qc) * VSTR;
            #pragma unroll
            for (int nt = 0; nt < 8; nt++) {
                const uint32_t b0 = __float_as_uint(Vs[tr0 + nt*8 + qr]);
                const uint32_t b1 = __float_as_uint(Vs[tr0 + VSTR + nt*8 + qr]);
                MMA_TF32(o[nt], a0, a1, a2, a3, b0, b1);
            }
        }
    }

    // ---- epilogue: normalize, split to bf16 hi/lo ctx ----
    const int b = bh >> 4;
    const int h = bh & 15;
    const float i0 = 1.f / l0;
    const float i1 = 1.f / l1;
    const size_t r0off = (size_t)(b*SS + qg_lo) * DM;
    const size_t r1off = (size_t)(b*SS + qg_hi) * DM;
    #pragma unroll
    for (int nt = 0; nt < 8; nt++) {
        const int d = h*64 + nt*8 + qc*2;
        float w0x = o[nt][0] * i0, w0y = o[nt][1] * i0;
        float w1x = o[nt][2] * i1, w1y = o[nt][3] * i1;
        __nv_bfloat162 h0 = __floats2bfloat162_rn(w0x, w0y);
        __nv_bfloat162 h1 = __floats2bfloat162_rn(w1x, w1y);
        __nv_bfloat162 l0v = __floats2bfloat162_rn(w0x - __bfloat162float(h0.x),
                                                   w0y - __bfloat162float(h0.y));
        __nv_bfloat162 l1v = __floats2bfloat162_rn(w1x - __bfloat162float(h1.x),
                                                   w1y - __bfloat162float(h1.y));
        *(__nv_bfloat162*)&g_chi[r0off + d] = h0;
        *(__nv_bfloat162*)&g_clo[r0off + d] = l0v;
        *(__nv_bfloat162*)&g_chi[r1off + d] = h1;
        *(__nv_bfloat162*)&g_clo[r1off + d] = l1v;
    }
}

// ============================================================
extern "C" void kernel_launch(void* const* d_in, const int* in_sizes, int n_in,
                              void* d_out, int out_size)
{
    const float* x  = (const float*)d_in[0];
    const float* Wq = (const float*)d_in[1];
    const float* bq = (const float*)d_in[2];
    const float* Wk = (const float*)d_in[3];
    const float* bk = (const float*)d_in[4];
    const float* Wv = (const float*)d_in[5];
    const float* bv = (const float*)d_in[6];
    const float* Wo = (const float*)d_in[7];
    const float* bo = (const float*)d_in[8];
    float* out = (float*)d_out;

    cudaFuncSetAttribute(gemm_tc<0>, cudaFuncAttributeMaxDynamicSharedMemorySize, GEMM_SMEM_BYTES);
    cudaFuncSetAttribute(gemm_tc<1>, cudaFuncAttributeMaxDynamicSharedMemorySize, GEMM_SMEM_BYTES);
    cudaFuncSetAttribute(attn_tc, cudaFuncAttributeMaxDynamicSharedMemorySize, ATT_SMEM_BYTES);

    prep_split<<<dim3(MM*DM/4/256, 5), 256>>>(x, Wq, Wk, Wv, Wo);
    gemm_tc<0><<<dim3(DM / 128, MM / 128, 3), 512, GEMM_SMEM_BYTES>>>(bq, bk, bv, nullptr);
    attn_tc<<<dim3(SS / 128, BB * NH), 256, ATT_SMEM_BYTES>>>();
    gemm_tc<1><<<dim3(DM / 128, MM / 128), 512, GEMM_SMEM_BYTES>>>(bo, nullptr, nullptr, out);
}